// round 1
// baseline (speedup 1.0000x reference)
#include <cuda_runtime.h>
#include <math.h>

// ---------------------------------------------------------------------------
// Problem constants
//   x: (2,16,1,128,128)
//   block0: 1->64,  128x128 -> pool -> 64x64
//   block1: 64->128, 64x64  -> pool -> 32x32
//   block2: 128->256,32x32  -> pool -> 16x16
//   ConvLSTM x2: cin=512 (256 x + 256 h), cout=1024, 3x3, 16x16, HID=256
//   out: z_seq (2,16,256,16,16) ++ z_last (2,256,16,16)
// ---------------------------------------------------------------------------

#define CHW2 65536      // 256*16*16
#define ZSTRIDE 262144  // 1024*16*16

typedef unsigned long long ull;

__device__ __forceinline__ ull pack2(float lo, float hi) {
    ull r; asm("mov.b64 %0, {%1,%2};" : "=l"(r) : "f"(lo), "f"(hi)); return r;
}
__device__ __forceinline__ void unpack2(ull v, float& lo, float& hi) {
    asm("mov.b64 {%0,%1}, %2;" : "=f"(lo), "=f"(hi) : "l"(v));
}
__device__ __forceinline__ ull fma2(ull a, ull b, ull c) {
    ull d; asm("fma.rn.f32x2 %0, %1, %2, %3;" : "=l"(d) : "l"(a), "l"(b), "l"(c));
    return d;
}
__device__ __forceinline__ float sigmoidf_(float x) { return 1.0f / (1.0f + expf(-x)); }

// ---------------------------------------------------------------------------
// Scratch (allocation-free: __device__ globals)
// ---------------------------------------------------------------------------
__device__ float g_f0[32 * 64 * 64 * 64];    // after block0
__device__ float g_f1[32 * 128 * 32 * 32];   // after block1
__device__ float g_f2[32 * 256 * 16 * 16];   // after block2 (CNN features)
__device__ float g_hs0[16 * 2 * 256 * 16 * 16]; // layer-0 hidden states across time
__device__ float g_z[2 * 1024 * 16 * 16];    // per-step conv output (gates pre-activation)
__device__ float g_h[2 * 256 * 16 * 16];     // current h state
__device__ float g_c[2 * 256 * 16 * 16];     // current c state

// ---------------------------------------------------------------------------
// Block 0: 1 input channel. One thread per pooled output.
// ---------------------------------------------------------------------------
__global__ void __launch_bounds__(256) conv0_pool(
    const float* __restrict__ x, const float* __restrict__ w,
    const float* __restrict__ bias, const float* __restrict__ g,
    const float* __restrict__ be, const float* __restrict__ m,
    const float* __restrict__ v)
{
    int idx = blockIdx.x * 256 + threadIdx.x;   // 32*64*64*64 = 8388608
    int pw = idx & 63;
    int ph = (idx >> 6) & 63;
    int oc = (idx >> 12) & 63;
    int n  = idx >> 18;

    float wr[9];
#pragma unroll
    for (int k = 0; k < 9; k++) wr[k] = w[oc * 9 + k];
    float s  = g[oc] * rsqrtf(v[oc] + 1e-5f);
    float cb = (bias[oc] - m[oc]) * s + be[oc];

    const float* xi = x + n * 16384;
    float mx = -1e30f;
#pragma unroll
    for (int dy0 = 0; dy0 < 2; dy0++) {
#pragma unroll
        for (int dx0 = 0; dx0 < 2; dx0++) {
            int oy = 2 * ph + dy0, ox = 2 * pw + dx0;
            float sum = 0.f;
#pragma unroll
            for (int ky = 0; ky < 3; ky++) {
                int iy = oy - 1 + ky;
                if (iy < 0 || iy >= 128) continue;
#pragma unroll
                for (int kx = 0; kx < 3; kx++) {
                    int ix = ox - 1 + kx;
                    if (ix < 0 || ix >= 128) continue;
                    sum = fmaf(xi[iy * 128 + ix], wr[ky * 3 + kx], sum);
                }
            }
            float y = fmaxf(fmaf(sum, s, cb), 0.f);
            mx = fmaxf(mx, y);
        }
    }
    g_f0[idx] = mx; // layout exactly (n, oc, ph, pw) with dims (32,64,64,64)
}

// ---------------------------------------------------------------------------
// Generic tiled conv + BN + ReLU + 2x2 maxpool.
// Block: 256 threads = 16x16 conv positions, 16 output channels per block.
// ---------------------------------------------------------------------------
template <int CIN, int S, int OCTOT>
__global__ void __launch_bounds__(256) cnn_conv_pool(
    const float* __restrict__ in, const float* __restrict__ w,
    const float* __restrict__ bias, const float* __restrict__ g,
    const float* __restrict__ be, const float* __restrict__ m,
    const float* __restrict__ v, float* __restrict__ out)
{
    constexpr int CH = 8;
    __shared__ float tile[CH][18][18];
    __shared__ ull   wp[CH][9][8];
    __shared__ float ssc[16], sbi[16];
    __shared__ float pbuf[16][16][16];

    const int tpr = S / 16;
    int tx = blockIdx.x % tpr, ty = blockIdx.x / tpr;
    int ocb = blockIdx.y * 16;
    int n   = blockIdx.z;
    int tid = threadIdx.x;
    int py = tid >> 4, px = tid & 15;

    if (tid < 16) {
        int oc = ocb + tid;
        float s = g[oc] * rsqrtf(v[oc] + 1e-5f);
        ssc[tid] = s;
        sbi[tid] = (bias[oc] - m[oc]) * s + be[oc];
    }

    ull acc[8];
#pragma unroll
    for (int p = 0; p < 8; p++) acc[p] = 0ULL;

    int oy0 = ty * 16, ox0 = tx * 16;
    for (int c0 = 0; c0 < CIN; c0 += CH) {
        for (int i = tid; i < CH * 324; i += 256) {
            int c = i / 324, r = (i % 324) / 18, col = i % 18;
            int gy = oy0 - 1 + r, gx = ox0 - 1 + col;
            float val = 0.f;
            if (gy >= 0 && gy < S && gx >= 0 && gx < S)
                val = in[((n * CIN + c0 + c) * S + gy) * S + gx];
            tile[c][r][col] = val;
        }
        for (int i = tid; i < CH * 72; i += 256) {
            int p = i & 7, k = (i >> 3) % 9, c = i / 72;
            const float* wb = w + ((size_t)(ocb + 2 * p) * CIN + (c0 + c)) * 9 + k;
            wp[c][k][p] = pack2(wb[0], wb[(size_t)CIN * 9]);
        }
        __syncthreads();
#pragma unroll 2
        for (int c = 0; c < CH; c++) {
            ull vv[9];
#pragma unroll
            for (int dy = 0; dy < 3; dy++)
#pragma unroll
                for (int dx = 0; dx < 3; dx++) {
                    float val = tile[c][py + dy][px + dx];
                    vv[dy * 3 + dx] = pack2(val, val);
                }
#pragma unroll
            for (int k = 0; k < 9; k++)
#pragma unroll
                for (int p = 0; p < 8; p++)
                    acc[p] = fma2(vv[k], wp[c][k][p], acc[p]);
        }
        __syncthreads();
    }

    float af[16];
#pragma unroll
    for (int p = 0; p < 8; p++) unpack2(acc[p], af[2 * p], af[2 * p + 1]);
#pragma unroll
    for (int j = 0; j < 16; j++)
        pbuf[j][py][px] = fmaxf(fmaf(af[j], ssc[j], sbi[j]), 0.f);
    __syncthreads();

    const int Sp = S / 2;
    for (int i = tid; i < 16 * 64; i += 256) {
        int oc = i >> 6, pp = i & 63, ph = pp >> 3, pw = pp & 7;
        float a  = pbuf[oc][2 * ph][2 * pw];
        float b2 = pbuf[oc][2 * ph][2 * pw + 1];
        float c2 = pbuf[oc][2 * ph + 1][2 * pw];
        float d  = pbuf[oc][2 * ph + 1][2 * pw + 1];
        float mx = fmaxf(fmaxf(a, b2), fmaxf(c2, d));
        out[((n * OCTOT + ocb + oc) * Sp + ty * 8 + ph) * Sp + tx * 8 + pw] = mx;
    }
}

// ---------------------------------------------------------------------------
// ConvLSTM gate conv: z = conv3x3(concat(x_t, h_prev), W) + b
// 16x16 spatial, cin=512 (first 256 from x source, last 256 from h state).
// Grid: (64 oc-groups, 2 batches). Block: 256 threads (16x16 positions).
// ---------------------------------------------------------------------------
__global__ void __launch_bounds__(256) lstm_conv(
    const float* __restrict__ w, const float* __restrict__ bias,
    int t, int layer)
{
    constexpr int CH = 8;
    __shared__ float tile[CH][18][18];
    __shared__ ull   wp[CH][9][8];
    __shared__ float sbi[16];

    int ocb = blockIdx.x * 16;
    int b   = blockIdx.y;
    int tid = threadIdx.x;
    int py = tid >> 4, px = tid & 15;

    if (tid < 16) sbi[tid] = bias[ocb + tid];

    // x source: layer 0 -> CNN features g_f2 (n = b*16 + t)
    //           layer 1 -> layer-0 hidden g_hs0 (t, b, ...)
    const float* xsrc;
    int xbstride;
    if (layer == 0) { xsrc = g_f2 + (size_t)t * CHW2; xbstride = 16 * CHW2; }
    else            { xsrc = g_hs0 + (size_t)t * 2 * CHW2; xbstride = CHW2; }

    ull acc[8];
#pragma unroll
    for (int p = 0; p < 8; p++) acc[p] = 0ULL;

    for (int c0 = 0; c0 < 512; c0 += CH) {
        const float* src = (c0 < 256)
            ? (xsrc + (size_t)b * xbstride + c0 * 256)
            : (g_h + (size_t)b * CHW2 + (c0 - 256) * 256);
        for (int i = tid; i < CH * 324; i += 256) {
            int c = i / 324, r = (i % 324) / 18, col = i % 18;
            int gy = r - 1, gx = col - 1;
            float val = 0.f;
            if (gy >= 0 && gy < 16 && gx >= 0 && gx < 16)
                val = src[c * 256 + gy * 16 + gx];
            tile[c][r][col] = val;
        }
        for (int i = tid; i < CH * 72; i += 256) {
            int p = i & 7, k = (i >> 3) % 9, c = i / 72;
            const float* wb = w + ((size_t)(ocb + 2 * p) * 512 + (c0 + c)) * 9 + k;
            wp[c][k][p] = pack2(wb[0], wb[512 * 9]);
        }
        __syncthreads();
#pragma unroll 2
        for (int c = 0; c < CH; c++) {
            ull vv[9];
#pragma unroll
            for (int dy = 0; dy < 3; dy++)
#pragma unroll
                for (int dx = 0; dx < 3; dx++) {
                    float val = tile[c][py + dy][px + dx];
                    vv[dy * 3 + dx] = pack2(val, val);
                }
#pragma unroll
            for (int k = 0; k < 9; k++)
#pragma unroll
                for (int p = 0; p < 8; p++)
                    acc[p] = fma2(vv[k], wp[c][k][p], acc[p]);
        }
        __syncthreads();
    }

    float af[16];
#pragma unroll
    for (int p = 0; p < 8; p++) unpack2(acc[p], af[2 * p], af[2 * p + 1]);
#pragma unroll
    for (int j = 0; j < 16; j++)
        g_z[(size_t)b * ZSTRIDE + (ocb + j) * 256 + py * 16 + px] = af[j] + sbi[j];
}

// ---------------------------------------------------------------------------
// Gate nonlinearities + state update. Writes h to per-layer destination.
//   layer 0: g_hs0[t]        layer 1: d_out z_seq slot at time t
// ---------------------------------------------------------------------------
__global__ void __launch_bounds__(256) lstm_gates(int t, int layer, float* __restrict__ out)
{
    int idx = blockIdx.x * 256 + threadIdx.x;  // 131072 = 2*256*16*16
    int inner = idx & 65535;
    int b = idx >> 16;
    const float* zb = g_z + (size_t)b * ZSTRIDE;

    float zi = zb[inner];
    float zf = zb[65536 + inner];
    float zo = zb[131072 + inner];
    float zg = zb[196608 + inner];

    float cn = sigmoidf_(zf) * g_c[idx] + sigmoidf_(zi) * tanhf(zg);
    float hn = sigmoidf_(zo) * tanhf(cn);
    g_c[idx] = cn;
    g_h[idx] = hn;

    if (layer == 0)
        g_hs0[(size_t)t * 2 * CHW2 + idx] = hn;                 // (t, b, c, y, x)
    else
        out[(size_t)b * 16 * CHW2 + (size_t)t * CHW2 + inner] = hn; // (b, t, c, y, x)
}

__global__ void __launch_bounds__(256) zero_state()
{
    int idx = blockIdx.x * 256 + threadIdx.x;  // 131072
    g_h[idx] = 0.f;
    g_c[idx] = 0.f;
}

__global__ void __launch_bounds__(256) copy_last(float* __restrict__ out)
{
    int idx = blockIdx.x * 256 + threadIdx.x;  // 131072
    int inner = idx & 65535;
    int b = idx >> 16;
    out[2097152 + idx] = out[(size_t)b * 16 * CHW2 + 15 * CHW2 + inner];
}

// ---------------------------------------------------------------------------
// Launch sequence (graph-capturable, default stream)
// ---------------------------------------------------------------------------
extern "C" void kernel_launch(void* const* d_in, const int* in_sizes, int n_in,
                              void* d_out, int out_size)
{
    const float* x   = (const float*)d_in[0];
    const float* w0  = (const float*)d_in[1];
    const float* b0  = (const float*)d_in[2];
    const float* g0  = (const float*)d_in[3];
    const float* be0 = (const float*)d_in[4];
    const float* m0  = (const float*)d_in[5];
    const float* v0  = (const float*)d_in[6];
    const float* w1  = (const float*)d_in[7];
    const float* b1  = (const float*)d_in[8];
    const float* g1  = (const float*)d_in[9];
    const float* be1 = (const float*)d_in[10];
    const float* m1  = (const float*)d_in[11];
    const float* v1  = (const float*)d_in[12];
    const float* w2  = (const float*)d_in[13];
    const float* b2  = (const float*)d_in[14];
    const float* g2  = (const float*)d_in[15];
    const float* be2 = (const float*)d_in[16];
    const float* m2  = (const float*)d_in[17];
    const float* v2  = (const float*)d_in[18];
    const float* lw0 = (const float*)d_in[19];
    const float* lb0 = (const float*)d_in[20];
    const float* lw1 = (const float*)d_in[21];
    const float* lb1 = (const float*)d_in[22];
    float* out = (float*)d_out;

    // CNN encoder over all 32 frames
    conv0_pool<<<32768, 256>>>(x, w0, b0, g0, be0, m0, v0);

    {
        float* f1ptr; cudaGetSymbolAddress((void**)&f1ptr, g_f1);
        float* f0ptr; cudaGetSymbolAddress((void**)&f0ptr, g_f0);
        float* f2ptr; cudaGetSymbolAddress((void**)&f2ptr, g_f2);
        cnn_conv_pool<64, 64, 128><<<dim3(16, 8, 32), 256>>>(f0ptr, w1, b1, g1, be1, m1, v1, f1ptr);
        cnn_conv_pool<128, 32, 256><<<dim3(4, 16, 32), 256>>>(f1ptr, w2, b2, g2, be2, m2, v2, f2ptr);
    }

    // ConvLSTM layer 0
    zero_state<<<512, 256>>>();
    for (int t = 0; t < 16; t++) {
        lstm_conv<<<dim3(64, 2), 256>>>(lw0, lb0, t, 0);
        lstm_gates<<<512, 256>>>(t, 0, out);
    }

    // ConvLSTM layer 1
    zero_state<<<512, 256>>>();
    for (int t = 0; t < 16; t++) {
        lstm_conv<<<dim3(64, 2), 256>>>(lw1, lb1, t, 1);
        lstm_gates<<<512, 256>>>(t, 1, out);
    }

    copy_last<<<512, 256>>>(out);
}

// round 6
// speedup vs baseline: 3.7351x; 3.7351x over previous
#include <cuda_runtime.h>
#include <cuda_fp16.h>
#include <math.h>
#include <stdint.h>

// ---------------------------------------------------------------------------
//   x: (2,16,1,128,128)
//   block0: 1->64,  128x128 -> pool -> 64x64
//   block1: 64->128, 64x64  -> pool -> 32x32
//   block2: 128->256,32x32  -> pool -> 16x16
//   ConvLSTM x2: cin=512 (256 x + 256 h), cout=1024, 3x3, 16x16, HID=256
//   out: z_seq (2,16,256,16,16) ++ z_last (2,256,16,16)
// LSTM conv as GEMM: Z_b[1024,256] = W[1024,4608] * B_b[4608,256]
//   k = s*512 + c, s=(dy+1)*3+(dx+1);  B[k][n] = in_c(y_n+dy, x_n+dx)
// 3xFP16 error-compensated mma.sync (hi/lo split of both operands):
//   D += Ah*Bh + Ah*Bl + Al*Bh   (Al*Bl dropped, ~2^-22 relative)
// ---------------------------------------------------------------------------

#define CHW2 65536          // 256*16*16
#define BHS  589824         // 9*256*256  (halfs per (t,b) or per b im2col slab)

typedef unsigned long long ull;

// ============================ PTX helpers ==================================
__device__ __forceinline__ uint32_t smem_u32(const void* p) {
    uint32_t a;
    asm("{ .reg .u64 t; cvta.to.shared.u64 t, %1; cvt.u32.u64 %0, t; }" : "=r"(a) : "l"(p));
    return a;
}
__device__ __forceinline__ void ldm_x4(uint32_t* r, uint32_t addr) {
    asm volatile("ldmatrix.sync.aligned.m8n8.x4.shared.b16 {%0,%1,%2,%3}, [%4];"
        : "=r"(r[0]), "=r"(r[1]), "=r"(r[2]), "=r"(r[3]) : "r"(addr));
}
__device__ __forceinline__ void ldm_x4t(uint32_t* r, uint32_t addr) {
    asm volatile("ldmatrix.sync.aligned.m8n8.x4.trans.shared.b16 {%0,%1,%2,%3}, [%4];"
        : "=r"(r[0]), "=r"(r[1]), "=r"(r[2]), "=r"(r[3]) : "r"(addr));
}
__device__ __forceinline__ void mma16816(float* d, const uint32_t* a, const uint32_t* b) {
    asm volatile(
        "mma.sync.aligned.m16n8k16.row.col.f32.f16.f16.f32 "
        "{%0,%1,%2,%3}, {%4,%5,%6,%7}, {%8,%9}, {%0,%1,%2,%3};"
        : "+f"(d[0]), "+f"(d[1]), "+f"(d[2]), "+f"(d[3])
        : "r"(a[0]), "r"(a[1]), "r"(a[2]), "r"(a[3]), "r"(b[0]), "r"(b[1]));
}
__device__ __forceinline__ void cp16(uint32_t sdst, const void* gsrc) {
    asm volatile("cp.async.cg.shared.global [%0], [%1], 16;" :: "r"(sdst), "l"(gsrc));
}
__device__ __forceinline__ void cp_commit() { asm volatile("cp.async.commit_group;"); }
template <int N> __device__ __forceinline__ void cp_wait() {
    asm volatile("cp.async.wait_group %0;" :: "n"(N));
}

__device__ __forceinline__ ull pack2(float lo, float hi) {
    ull r; asm("mov.b64 %0, {%1,%2};" : "=l"(r) : "f"(lo), "f"(hi)); return r;
}
__device__ __forceinline__ void unpack2(ull v, float& lo, float& hi) {
    asm("mov.b64 {%0,%1}, %2;" : "=f"(lo), "=f"(hi) : "l"(v));
}
__device__ __forceinline__ ull fma2(ull a, ull b, ull c) {
    ull d; asm("fma.rn.f32x2 %0, %1, %2, %3;" : "=l"(d) : "l"(a), "l"(b), "l"(c));
    return d;
}
__device__ __forceinline__ float sigmoidf_(float x) { return 1.0f / (1.0f + expf(-x)); }

// ---------------------------------------------------------------------------
// Scratch (__device__ globals; zero-init at load; aligned for 16B access)
// ---------------------------------------------------------------------------
__device__ __align__(256) float  g_f0[32 * 64 * 64 * 64];
__device__ __align__(256) float  g_f1[32 * 128 * 32 * 32];
__device__ __align__(256) float  g_f2[32 * 256 * 16 * 16];
__device__ __align__(256) __half g_wph[2 * 288 * 1024 * 16];  // weights hi [layer][G][oc][16]
__device__ __align__(256) __half g_wpl[2 * 288 * 1024 * 16];  // weights lo
__device__ __align__(256) __half g_bx0h[32 * BHS];            // L0 x im2col hi [(t*2+b)][s][c][n]
__device__ __align__(256) __half g_bx0l[32 * BHS];            // L0 x im2col lo
__device__ __align__(256) __half g_bx1h[32 * BHS];            // L1 x im2col hi
__device__ __align__(256) __half g_bx1l[32 * BHS];            // L1 x im2col lo
__device__ __align__(256) __half g_bhh[2 * BHS];              // h im2col hi [b][s][c][n]
__device__ __align__(256) __half g_bhl[2 * BHS];              // h im2col lo
__device__ __align__(256) float  g_c[2 * 256 * 16 * 16];      // cell state fp32
__device__ __align__(256) float  g_zp[4 * 2 * 1024 * 256];    // K-split partials

// ---------------------------------------------------------------------------
// Weight prepack: fp32 -> (hi, lo) fp16 pair in [layer][G][oc][16] layout
// ---------------------------------------------------------------------------
__global__ void __launch_bounds__(256) prepack_w(const float* __restrict__ lw, int layer)
{
    int idx = blockIdx.x * 256 + threadIdx.x;  // 4718592
    int u  = idx & 15;
    int oc = (idx >> 4) & 1023;
    int G  = idx >> 14;
    int k  = G * 16 + u;
    int s  = k >> 9;
    int c  = k & 511;
    float w = lw[((size_t)oc * 512 + c) * 9 + s];
    __half hi = __float2half(w);
    size_t o = (size_t)layer * 4718592 + idx;
    g_wph[o] = hi;
    g_wpl[o] = __float2half(w - __half2float(hi));
}

// ---------------------------------------------------------------------------
// Build layer0 x im2col (hi/lo) from CNN features. 32*BHS elements.
// ---------------------------------------------------------------------------
__global__ void __launch_bounds__(256) build_bx0()
{
    int idx = blockIdx.x * 256 + threadIdx.x;   // < 18874368
    int n   = idx & 255;
    int c   = (idx >> 8) & 255;
    int rem = idx >> 16;        // 0..287 = tb*9 + s
    int s   = rem % 9;
    int tb  = rem / 9;
    int t   = tb >> 1, b = tb & 1;
    int dy  = s / 3 - 1, dx = s % 3 - 1;
    int iy  = (n >> 4) + dy, ix = (n & 15) + dx;
    float val = 0.f;
    if (iy >= 0 && iy < 16 && ix >= 0 && ix < 16)
        val = g_f2[(((size_t)(b * 16 + t) * 256 + c) << 8) + iy * 16 + ix];
    __half hi = __float2half(val);
    g_bx0h[idx] = hi;
    g_bx0l[idx] = __float2half(val - __half2float(hi));
}

// ---------------------------------------------------------------------------
// Block 0: 1 input channel. One thread per pooled output.
// ---------------------------------------------------------------------------
__global__ void __launch_bounds__(256) conv0_pool(
    const float* __restrict__ x, const float* __restrict__ w,
    const float* __restrict__ bias, const float* __restrict__ g,
    const float* __restrict__ be, const float* __restrict__ m,
    const float* __restrict__ v)
{
    int idx = blockIdx.x * 256 + threadIdx.x;   // 8388608
    int pw = idx & 63;
    int ph = (idx >> 6) & 63;
    int oc = (idx >> 12) & 63;
    int n  = idx >> 18;

    float wr[9];
#pragma unroll
    for (int k = 0; k < 9; k++) wr[k] = w[oc * 9 + k];
    float s  = g[oc] * rsqrtf(v[oc] + 1e-5f);
    float cb = (bias[oc] - m[oc]) * s + be[oc];

    const float* xi = x + n * 16384;
    float mx = -1e30f;
#pragma unroll
    for (int dy0 = 0; dy0 < 2; dy0++) {
#pragma unroll
        for (int dx0 = 0; dx0 < 2; dx0++) {
            int oy = 2 * ph + dy0, ox = 2 * pw + dx0;
            float sum = 0.f;
#pragma unroll
            for (int ky = 0; ky < 3; ky++) {
                int iy = oy - 1 + ky;
                if (iy < 0 || iy >= 128) continue;
#pragma unroll
                for (int kx = 0; kx < 3; kx++) {
                    int ix = ox - 1 + kx;
                    if (ix < 0 || ix >= 128) continue;
                    sum = fmaf(xi[iy * 128 + ix], wr[ky * 3 + kx], sum);
                }
            }
            float y = fmaxf(fmaf(sum, s, cb), 0.f);
            mx = fmaxf(mx, y);
        }
    }
    g_f0[idx] = mx;
}

// ---------------------------------------------------------------------------
// Generic tiled conv + BN + ReLU + 2x2 maxpool (fp32 SIMT, f32x2 packed)
// ---------------------------------------------------------------------------
template <int CIN, int S, int OCTOT>
__global__ void __launch_bounds__(256) cnn_conv_pool(
    const float* __restrict__ in, const float* __restrict__ w,
    const float* __restrict__ bias, const float* __restrict__ g,
    const float* __restrict__ be, const float* __restrict__ m,
    const float* __restrict__ v, float* __restrict__ out)
{
    constexpr int CH = 8;
    __shared__ float tile[CH][18][18];
    __shared__ ull   wp[CH][9][8];
    __shared__ float ssc[16], sbi[16];
    __shared__ float pbuf[16][16][16];

    const int tpr = S / 16;
    int tx = blockIdx.x % tpr, ty = blockIdx.x / tpr;
    int ocb = blockIdx.y * 16;
    int n   = blockIdx.z;
    int tid = threadIdx.x;
    int py = tid >> 4, px = tid & 15;

    if (tid < 16) {
        int oc = ocb + tid;
        float s = g[oc] * rsqrtf(v[oc] + 1e-5f);
        ssc[tid] = s;
        sbi[tid] = (bias[oc] - m[oc]) * s + be[oc];
    }

    ull acc[8];
#pragma unroll
    for (int p = 0; p < 8; p++) acc[p] = 0ULL;

    int oy0 = ty * 16, ox0 = tx * 16;
    for (int c0 = 0; c0 < CIN; c0 += CH) {
        for (int i = tid; i < CH * 324; i += 256) {
            int c = i / 324, r = (i % 324) / 18, col = i % 18;
            int gy = oy0 - 1 + r, gx = ox0 - 1 + col;
            float val = 0.f;
            if (gy >= 0 && gy < S && gx >= 0 && gx < S)
                val = in[((n * CIN + c0 + c) * S + gy) * S + gx];
            tile[c][r][col] = val;
        }
        for (int i = tid; i < CH * 72; i += 256) {
            int p = i & 7, k = (i >> 3) % 9, c = i / 72;
            const float* wb = w + ((size_t)(ocb + 2 * p) * CIN + (c0 + c)) * 9 + k;
            wp[c][k][p] = pack2(wb[0], wb[(size_t)CIN * 9]);
        }
        __syncthreads();
#pragma unroll 2
        for (int c = 0; c < CH; c++) {
            ull vv[9];
#pragma unroll
            for (int dy = 0; dy < 3; dy++)
#pragma unroll
                for (int dx = 0; dx < 3; dx++) {
                    float val = tile[c][py + dy][px + dx];
                    vv[dy * 3 + dx] = pack2(val, val);
                }
#pragma unroll
            for (int k = 0; k < 9; k++)
#pragma unroll
                for (int p = 0; p < 8; p++)
                    acc[p] = fma2(vv[k], wp[c][k][p], acc[p]);
        }
        __syncthreads();
    }

    float af[16];
#pragma unroll
    for (int p = 0; p < 8; p++) unpack2(acc[p], af[2 * p], af[2 * p + 1]);
#pragma unroll
    for (int j = 0; j < 16; j++)
        pbuf[j][py][px] = fmaxf(fmaf(af[j], ssc[j], sbi[j]), 0.f);
    __syncthreads();

    const int Sp = S / 2;
    for (int i = tid; i < 16 * 64; i += 256) {
        int oc = i >> 6, pp = i & 63, ph = pp >> 3, pw = pp & 7;
        float a  = pbuf[oc][2 * ph][2 * pw];
        float b2 = pbuf[oc][2 * ph][2 * pw + 1];
        float c2 = pbuf[oc][2 * ph + 1][2 * pw];
        float d  = pbuf[oc][2 * ph + 1][2 * pw + 1];
        float mx = fmaxf(fmaxf(a, b2), fmaxf(c2, d));
        out[((n * OCTOT + ocb + oc) * Sp + ty * 8 + ph) * Sp + tx * 8 + pw] = mx;
    }
}

// ---------------------------------------------------------------------------
// ConvLSTM gate conv via 3xFP16 mma.sync GEMM.
// Grid: (8 mtiles, 4 = ntile+2*b, 4 ksplits), 256 threads (8 warps).
// CTA tile M=128 (oc), N=128 (pos), K=1152 (72 k16 chunks).
// Warp grid 4(m) x 2(n); warp tile 32x64.
// Per chunk: D += Ah*Bh + Ah*Bl + Al*Bh  (48 MMAs/warp).
// ---------------------------------------------------------------------------
__global__ void __launch_bounds__(256) lstm_mma(
    const __half* __restrict__ wph, const __half* __restrict__ wpl,
    const __half* __restrict__ bxh_t, const __half* __restrict__ bxl_t)
{
    __shared__ __align__(16) __half Ah[2][128 * 24];
    __shared__ __align__(16) __half Al[2][128 * 24];
    __shared__ __align__(16) __half Bh[2][16 * 136];
    __shared__ __align__(16) __half Bl[2][16 * 136];

    int tid  = threadIdx.x;
    int lane = tid & 31;
    int wid  = tid >> 5;
    int wm = wid & 3, wn = wid >> 2;

    int mtile = blockIdx.x;
    int ntile = blockIdx.y & 1;
    int b     = blockIdx.y >> 1;
    int split = blockIdx.z;
    int ocb   = mtile * 128;

    const __half* bxh = bxh_t + (size_t)b * BHS;
    const __half* bxl = bxl_t + (size_t)b * BHS;
    const __half* bhh = g_bhh + (size_t)b * BHS;
    const __half* bhl = g_bhl + (size_t)b * BHS;

    // staging thread roles
    int arow = tid >> 1, au = tid & 1;
    uint32_t ah_dst[2], al_dst[2], bh_dst[2], bl_dst[2];
    {
        uint32_t ao = arow * 48 + au * 16;
        int br_ = tid >> 4, bc_ = tid & 15;
        uint32_t bo = br_ * 272 + bc_ * 16;
        ah_dst[0] = smem_u32(&Ah[0][0]) + ao; ah_dst[1] = smem_u32(&Ah[1][0]) + ao;
        al_dst[0] = smem_u32(&Al[0][0]) + ao; al_dst[1] = smem_u32(&Al[1][0]) + ao;
        bh_dst[0] = smem_u32(&Bh[0][0]) + bo; bh_dst[1] = smem_u32(&Bh[1][0]) + bo;
        bl_dst[0] = smem_u32(&Bl[0][0]) + bo; bl_dst[1] = smem_u32(&Bl[1][0]) + bo;
    }
    size_t a_off_elem = (size_t)(arow + ocb) * 16 + au * 8;   // + G*16384
    int b_src_off = (tid >> 4) * 256 + ntile * 128 + (tid & 15) * 8;

    // ldmatrix lane address offsets (bytes, within buffer)
    int quad = lane >> 3, l7 = lane & 7;
    uint32_t a_off[2], b_off[4];
    {
        int rsub = ((quad & 1) << 3) + l7;
        int ksub = (quad >> 1) << 4;
#pragma unroll
        for (int mi = 0; mi < 2; mi++)
            a_off[mi] = (uint32_t)((wm * 32 + mi * 16 + rsub) * 48 + ksub);
        int krow = ((quad & 1) << 3) + l7;
        int nsub = (quad >> 1) << 3;
#pragma unroll
        for (int ni2 = 0; ni2 < 4; ni2++)
            b_off[ni2] = (uint32_t)(krow * 272 + (wn * 64 + ni2 * 16 + nsub) * 2);
    }
    uint32_t ahb[2] = { smem_u32(&Ah[0][0]), smem_u32(&Ah[1][0]) };
    uint32_t alb[2] = { smem_u32(&Al[0][0]), smem_u32(&Al[1][0]) };
    uint32_t bhb[2] = { smem_u32(&Bh[0][0]), smem_u32(&Bh[1][0]) };
    uint32_t blb[2] = { smem_u32(&Bl[0][0]), smem_u32(&Bl[1][0]) };

    float acc[2][8][4];
#pragma unroll
    for (int mi = 0; mi < 2; mi++)
#pragma unroll
        for (int ni = 0; ni < 8; ni++)
#pragma unroll
            for (int q = 0; q < 4; q++) acc[mi][ni][q] = 0.f;

    auto stage = [&](int j, int buf) {
        int G  = split * 72 + j;
        int s  = G >> 5;
        int c0 = (G & 31) << 4;
        bool xh = (c0 < 256);
        size_t srow = ((size_t)(s * 256 + (xh ? c0 : c0 - 256)) << 8);
        const __half* bsh = (xh ? bxh : bhh) + srow;
        const __half* bsl = (xh ? bxl : bhl) + srow;
        cp16(ah_dst[buf], wph + (size_t)G * 16384 + a_off_elem);
        cp16(al_dst[buf], wpl + (size_t)G * 16384 + a_off_elem);
        cp16(bh_dst[buf], bsh + b_src_off);
        cp16(bl_dst[buf], bsl + b_src_off);
        cp_commit();
    };

    stage(0, 0);
    stage(1, 1);

    for (int j = 0; j < 72; j++) {
        if (j < 71) cp_wait<1>(); else cp_wait<0>();
        __syncthreads();

        int buf = j & 1;
        uint32_t ah[2][4], al[2][4], bh_[4][4], bl_[4][4];
#pragma unroll
        for (int mi = 0; mi < 2; mi++) {
            ldm_x4(ah[mi], ahb[buf] + a_off[mi]);
            ldm_x4(al[mi], alb[buf] + a_off[mi]);
        }
#pragma unroll
        for (int ni2 = 0; ni2 < 4; ni2++) {
            ldm_x4t(bh_[ni2], bhb[buf] + b_off[ni2]);
            ldm_x4t(bl_[ni2], blb[buf] + b_off[ni2]);
        }
#pragma unroll
        for (int mi = 0; mi < 2; mi++)
#pragma unroll
            for (int ni = 0; ni < 8; ni++) {
                const uint32_t* bhf = &bh_[ni >> 1][(ni & 1) * 2];
                const uint32_t* blf = &bl_[ni >> 1][(ni & 1) * 2];
                mma16816(acc[mi][ni], ah[mi], bhf);
                mma16816(acc[mi][ni], ah[mi], blf);
                mma16816(acc[mi][ni], al[mi], bhf);
            }

        __syncthreads();
        if (j + 2 < 72) stage(j + 2, buf);
    }

    // ---- epilogue: write fp32 partials ----
    int gq = lane >> 2, tq = lane & 3;
    float* zbase = g_zp + ((size_t)(split * 2 + b) * 1024) * 256;
    int row0 = ocb + wm * 32 + gq;
    int col0 = ntile * 128 + wn * 64 + 2 * tq;
#pragma unroll
    for (int mi = 0; mi < 2; mi++)
#pragma unroll
        for (int ni = 0; ni < 8; ni++) {
            int r = row0 + mi * 16;
            int cc = col0 + ni * 8;
            *(float2*)(zbase + (size_t)r * 256 + cc)       = make_float2(acc[mi][ni][0], acc[mi][ni][1]);
            *(float2*)(zbase + (size_t)(r + 8) * 256 + cc) = make_float2(acc[mi][ni][2], acc[mi][ni][3]);
        }
}

// ---------------------------------------------------------------------------
// Gates: sum 4 K-split partials + bias, nonlinearities, state update,
// scatter h (hi/lo) into im2col buffers (bh always; bx1 when layer 0).
// ---------------------------------------------------------------------------
__global__ void __launch_bounds__(256) lstm_gates(int t, int layer,
                                                  const float* __restrict__ lb,
                                                  float* __restrict__ out)
{
    int idx = blockIdx.x * 256 + threadIdx.x;  // 131072
    int inner = idx & 65535;
    int b = idx >> 16;
    int c = inner >> 8;
    int pos = inner & 255;

    float zi = lb[c], zf = lb[c + 256], zo = lb[c + 512], zg = lb[c + 768];
#pragma unroll
    for (int s = 0; s < 4; s++) {
        const float* zb = g_zp + ((size_t)s * 2 + b) * 1024 * 256;
        zi += zb[(size_t)(c)       * 256 + pos];
        zf += zb[(size_t)(c + 256) * 256 + pos];
        zo += zb[(size_t)(c + 512) * 256 + pos];
        zg += zb[(size_t)(c + 768) * 256 + pos];
    }

    float cn = sigmoidf_(zf) * g_c[idx] + sigmoidf_(zi) * tanhf(zg);
    float hn = sigmoidf_(zo) * tanhf(cn);
    g_c[idx] = cn;

    __half hh = __float2half(hn);
    __half hl = __float2half(hn - __half2float(hh));
    int y = pos >> 4, x = pos & 15;
    __half* bhhp = g_bhh + (size_t)b * BHS;
    __half* bhlp = g_bhl + (size_t)b * BHS;
    __half* bxhp = g_bx1h + (size_t)(t * 2 + b) * BHS;
    __half* bxlp = g_bx1l + (size_t)(t * 2 + b) * BHS;
#pragma unroll
    for (int s = 0; s < 9; s++) {
        int dy = s / 3 - 1, dx = s % 3 - 1;
        int ny = y - dy, nx = x - dx;
        if (ny >= 0 && ny < 16 && nx >= 0 && nx < 16) {
            int o = ((s * 256 + c) << 8) + ny * 16 + nx;
            bhhp[o] = hh;
            bhlp[o] = hl;
            if (layer == 0) { bxhp[o] = hh; bxlp[o] = hl; }
        }
    }

    if (layer == 1)
        out[(size_t)b * 16 * CHW2 + (size_t)t * CHW2 + inner] = hn;
}

// zero c state and h im2col buffers
__global__ void __launch_bounds__(256) zero_state()
{
    int idx = blockIdx.x * 256 + threadIdx.x;   // 1179648
    if (idx < 131072) g_c[idx] = 0.f;
    g_bhh[idx] = __float2half(0.f);
    g_bhl[idx] = __float2half(0.f);
}

__global__ void __launch_bounds__(256) copy_last(float* __restrict__ out)
{
    int idx = blockIdx.x * 256 + threadIdx.x;   // 131072
    int inner = idx & 65535;
    int b = idx >> 16;
    out[2097152 + idx] = out[(size_t)b * 16 * CHW2 + 15 * CHW2 + inner];
}

// ---------------------------------------------------------------------------
// Launch sequence (graph-capturable)
// ---------------------------------------------------------------------------
extern "C" void kernel_launch(void* const* d_in, const int* in_sizes, int n_in,
                              void* d_out, int out_size)
{
    const float* x   = (const float*)d_in[0];
    const float* w0  = (const float*)d_in[1];
    const float* b0  = (const float*)d_in[2];
    const float* g0  = (const float*)d_in[3];
    const float* be0 = (const float*)d_in[4];
    const float* m0  = (const float*)d_in[5];
    const float* v0  = (const float*)d_in[6];
    const float* w1  = (const float*)d_in[7];
    const float* b1  = (const float*)d_in[8];
    const float* g1  = (const float*)d_in[9];
    const float* be1 = (const float*)d_in[10];
    const float* m1  = (const float*)d_in[11];
    const float* v1  = (const float*)d_in[12];
    const float* w2  = (const float*)d_in[13];
    const float* b2  = (const float*)d_in[14];
    const float* g2  = (const float*)d_in[15];
    const float* be2 = (const float*)d_in[16];
    const float* m2  = (const float*)d_in[17];
    const float* v2  = (const float*)d_in[18];
    const float* lw0 = (const float*)d_in[19];
    const float* lb0 = (const float*)d_in[20];
    const float* lw1 = (const float*)d_in[21];
    const float* lb1 = (const float*)d_in[22];
    float* out = (float*)d_out;

    float* f0ptr; cudaGetSymbolAddress((void**)&f0ptr, g_f0);
    float* f1ptr; cudaGetSymbolAddress((void**)&f1ptr, g_f1);
    float* f2ptr; cudaGetSymbolAddress((void**)&f2ptr, g_f2);
    __half* wphptr; cudaGetSymbolAddress((void**)&wphptr, g_wph);
    __half* wplptr; cudaGetSymbolAddress((void**)&wplptr, g_wpl);
    __half* bx0hptr; cudaGetSymbolAddress((void**)&bx0hptr, g_bx0h);
    __half* bx0lptr; cudaGetSymbolAddress((void**)&bx0lptr, g_bx0l);
    __half* bx1hptr; cudaGetSymbolAddress((void**)&bx1hptr, g_bx1h);
    __half* bx1lptr; cudaGetSymbolAddress((void**)&bx1lptr, g_bx1l);

    // weight prepack (hi/lo fp16, chunk-major layout)
    prepack_w<<<18432, 256>>>(lw0, 0);
    prepack_w<<<18432, 256>>>(lw1, 1);

    // CNN encoder over all 32 frames
    conv0_pool<<<32768, 256>>>(x, w0, b0, g0, be0, m0, v0);
    cnn_conv_pool<64, 64, 128><<<dim3(16, 8, 32), 256>>>(f0ptr, w1, b1, g1, be1, m1, v1, f1ptr);
    cnn_conv_pool<128, 32, 256><<<dim3(4, 16, 32), 256>>>(f1ptr, w2, b2, g2, be2, m2, v2, f2ptr);

    // hi/lo fp16 im2col of CNN features: 32*BHS / 256 = 73728 blocks
    build_bx0<<<73728, 256>>>();

    // ConvLSTM layer 0
    zero_state<<<4608, 256>>>();
    for (int t = 0; t < 16; t++) {
        lstm_mma<<<dim3(8, 4, 4), 256>>>(wphptr, wplptr,
                                         bx0hptr + (size_t)t * 2 * BHS,
                                         bx0lptr + (size_t)t * 2 * BHS);
        lstm_gates<<<512, 256>>>(t, 0, lb0, out);
    }

    // ConvLSTM layer 1
    zero_state<<<4608, 256>>>();
    for (int t = 0; t < 16; t++) {
        lstm_mma<<<dim3(8, 4, 4), 256>>>(wphptr + (size_t)288 * 1024 * 16,
                                         wplptr + (size_t)288 * 1024 * 16,
                                         bx1hptr + (size_t)t * 2 * BHS,
                                         bx1lptr + (size_t)t * 2 * BHS);
        lstm_gates<<<512, 256>>>(t, 1, lb1, out);
    }

    copy_last<<<512, 256>>>(out);
}

// round 7
// speedup vs baseline: 4.2763x; 1.1449x over previous
#include <cuda_runtime.h>
#include <cuda_fp16.h>
#include <math.h>
#include <stdint.h>

// ---------------------------------------------------------------------------
//   x: (2,16,1,128,128)
//   block0: 1->64,  128x128 -> pool -> 64x64
//   block1: 64->128, 64x64  -> pool -> 32x32
//   block2: 128->256,32x32  -> pool -> 16x16
//   ConvLSTM x2: cin=512 (256 x + 256 h), cout=1024, 3x3, 16x16, HID=256
//   out: z_seq (2,16,256,16,16) ++ z_last (2,256,16,16)
// LSTM conv as GEMM: Z_b[1024,256] = W[1024,4608] * B_b[4608,256]
//   k = s*512 + c, s=(dy+1)*3+(dx+1);  B[k][n] = in_c(y_n+dy, x_n+dx)
// 3xFP16 error-compensated mma.sync:  D += Ah*Bh + Ah*Bl + Al*Bh
// ---------------------------------------------------------------------------

#define CHW2 65536          // 256*16*16
#define BHS  589824         // 9*256*256  (halfs per (t,b) or per b im2col slab)

typedef unsigned long long ull;

// ============================ PTX helpers ==================================
__device__ __forceinline__ uint32_t smem_u32(const void* p) {
    uint32_t a;
    asm("{ .reg .u64 t; cvta.to.shared.u64 t, %1; cvt.u32.u64 %0, t; }" : "=r"(a) : "l"(p));
    return a;
}
__device__ __forceinline__ void ldm_x4(uint32_t* r, uint32_t addr) {
    asm volatile("ldmatrix.sync.aligned.m8n8.x4.shared.b16 {%0,%1,%2,%3}, [%4];"
        : "=r"(r[0]), "=r"(r[1]), "=r"(r[2]), "=r"(r[3]) : "r"(addr));
}
__device__ __forceinline__ void ldm_x4t(uint32_t* r, uint32_t addr) {
    asm volatile("ldmatrix.sync.aligned.m8n8.x4.trans.shared.b16 {%0,%1,%2,%3}, [%4];"
        : "=r"(r[0]), "=r"(r[1]), "=r"(r[2]), "=r"(r[3]) : "r"(addr));
}
__device__ __forceinline__ void mma16816(float* d, const uint32_t* a, const uint32_t* b) {
    asm volatile(
        "mma.sync.aligned.m16n8k16.row.col.f32.f16.f16.f32 "
        "{%0,%1,%2,%3}, {%4,%5,%6,%7}, {%8,%9}, {%0,%1,%2,%3};"
        : "+f"(d[0]), "+f"(d[1]), "+f"(d[2]), "+f"(d[3])
        : "r"(a[0]), "r"(a[1]), "r"(a[2]), "r"(a[3]), "r"(b[0]), "r"(b[1]));
}
__device__ __forceinline__ void cp16(uint32_t sdst, const void* gsrc) {
    asm volatile("cp.async.cg.shared.global [%0], [%1], 16;" :: "r"(sdst), "l"(gsrc));
}
__device__ __forceinline__ void cp_commit() { asm volatile("cp.async.commit_group;"); }
template <int N> __device__ __forceinline__ void cp_wait() {
    asm volatile("cp.async.wait_group %0;" :: "n"(N));
}

__device__ __forceinline__ ull pack2(float lo, float hi) {
    ull r; asm("mov.b64 %0, {%1,%2};" : "=l"(r) : "f"(lo), "f"(hi)); return r;
}
__device__ __forceinline__ void unpack2(ull v, float& lo, float& hi) {
    asm("mov.b64 {%0,%1}, %2;" : "=f"(lo), "=f"(hi) : "l"(v));
}
__device__ __forceinline__ ull fma2(ull a, ull b, ull c) {
    ull d; asm("fma.rn.f32x2 %0, %1, %2, %3;" : "=l"(d) : "l"(a), "l"(b), "l"(c));
    return d;
}
__device__ __forceinline__ float sigmoidf_(float x) { return 1.0f / (1.0f + expf(-x)); }

// ---------------------------------------------------------------------------
// Scratch (__device__ globals; zero-init at load; aligned for 16B access)
// ---------------------------------------------------------------------------
__device__ __align__(256) float  g_f0[32 * 64 * 64 * 64];
__device__ __align__(256) float  g_f1[32 * 128 * 32 * 32];
__device__ __align__(256) float  g_f2[32 * 256 * 16 * 16];
__device__ __align__(256) __half g_wph[2 * 288 * 1024 * 16];  // weights hi [layer][G][oc][16]
__device__ __align__(256) __half g_wpl[2 * 288 * 1024 * 16];  // weights lo
__device__ __align__(256) __half g_bx0h[32 * BHS];            // L0 x im2col hi [(t*2+b)][s][c][n]
__device__ __align__(256) __half g_bx0l[32 * BHS];            // L0 x im2col lo
__device__ __align__(256) __half g_bx1h[32 * BHS];            // L1 x im2col hi
__device__ __align__(256) __half g_bx1l[32 * BHS];            // L1 x im2col lo
__device__ __align__(256) __half g_bhh[2 * BHS];              // h im2col hi [b][s][c][n]
__device__ __align__(256) __half g_bhl[2 * BHS];              // h im2col lo
__device__ __align__(256) float  g_c[2 * 256 * 16 * 16];      // cell state fp32
__device__ __align__(256) float  g_zp[4 * 2 * 1024 * 256];    // K-split partials

// ---------------------------------------------------------------------------
// Weight prepack: fp32 -> (hi, lo) fp16 pair in [layer][G][oc][16] layout
// ---------------------------------------------------------------------------
__global__ void __launch_bounds__(256) prepack_w(const float* __restrict__ lw, int layer)
{
    int idx = blockIdx.x * 256 + threadIdx.x;  // 4718592
    int u  = idx & 15;
    int oc = (idx >> 4) & 1023;
    int G  = idx >> 14;
    int k  = G * 16 + u;
    int s  = k >> 9;
    int c  = k & 511;
    float w = lw[((size_t)oc * 512 + c) * 9 + s];
    __half hi = __float2half(w);
    size_t o = (size_t)layer * 4718592 + idx;
    g_wph[o] = hi;
    g_wpl[o] = __float2half(w - __half2float(hi));
}

// ---------------------------------------------------------------------------
// Build layer0 x im2col (hi/lo) from CNN features. 32*BHS elements.
// ---------------------------------------------------------------------------
__global__ void __launch_bounds__(256) build_bx0()
{
    int idx = blockIdx.x * 256 + threadIdx.x;   // < 18874368
    int n   = idx & 255;
    int c   = (idx >> 8) & 255;
    int rem = idx >> 16;        // 0..287 = tb*9 + s
    int s   = rem % 9;
    int tb  = rem / 9;
    int t   = tb >> 1, b = tb & 1;
    int dy  = s / 3 - 1, dx = s % 3 - 1;
    int iy  = (n >> 4) + dy, ix = (n & 15) + dx;
    float val = 0.f;
    if (iy >= 0 && iy < 16 && ix >= 0 && ix < 16)
        val = g_f2[(((size_t)(b * 16 + t) * 256 + c) << 8) + iy * 16 + ix];
    __half hi = __float2half(val);
    g_bx0h[idx] = hi;
    g_bx0l[idx] = __float2half(val - __half2float(hi));
}

// ---------------------------------------------------------------------------
// Block 0: 1 input channel. One thread per pooled output.
// ---------------------------------------------------------------------------
__global__ void __launch_bounds__(256) conv0_pool(
    const float* __restrict__ x, const float* __restrict__ w,
    const float* __restrict__ bias, const float* __restrict__ g,
    const float* __restrict__ be, const float* __restrict__ m,
    const float* __restrict__ v)
{
    int idx = blockIdx.x * 256 + threadIdx.x;   // 8388608
    int pw = idx & 63;
    int ph = (idx >> 6) & 63;
    int oc = (idx >> 12) & 63;
    int n  = idx >> 18;

    float wr[9];
#pragma unroll
    for (int k = 0; k < 9; k++) wr[k] = w[oc * 9 + k];
    float s  = g[oc] * rsqrtf(v[oc] + 1e-5f);
    float cb = (bias[oc] - m[oc]) * s + be[oc];

    const float* xi = x + n * 16384;
    float mx = -1e30f;
#pragma unroll
    for (int dy0 = 0; dy0 < 2; dy0++) {
#pragma unroll
        for (int dx0 = 0; dx0 < 2; dx0++) {
            int oy = 2 * ph + dy0, ox = 2 * pw + dx0;
            float sum = 0.f;
#pragma unroll
            for (int ky = 0; ky < 3; ky++) {
                int iy = oy - 1 + ky;
                if (iy < 0 || iy >= 128) continue;
#pragma unroll
                for (int kx = 0; kx < 3; kx++) {
                    int ix = ox - 1 + kx;
                    if (ix < 0 || ix >= 128) continue;
                    sum = fmaf(xi[iy * 128 + ix], wr[ky * 3 + kx], sum);
                }
            }
            float y = fmaxf(fmaf(sum, s, cb), 0.f);
            mx = fmaxf(mx, y);
        }
    }
    g_f0[idx] = mx;
}

// ---------------------------------------------------------------------------
// Tiled conv + BN + ReLU + 2x2 maxpool, fp32 SIMT, fma-bound layout:
//  - 256 threads, tile = 16 rows x 32 cols of conv positions, 16 oc per CTA
//  - each thread: 2 adjacent positions (x0, x0+1) -> in-register h-pool
//  - weights via LDS.128 (2 fma2 operands per load)
//  per channel per thread: 144 fma2 vs 36 LDS.128 + 6 LDS.64
// ---------------------------------------------------------------------------
template <int CIN, int S, int OCTOT>
__global__ void __launch_bounds__(256, 2) cnn_conv_pool(
    const float* __restrict__ in, const float* __restrict__ w,
    const float* __restrict__ bias, const float* __restrict__ g,
    const float* __restrict__ be, const float* __restrict__ m,
    const float* __restrict__ v, float* __restrict__ out)
{
    constexpr int CH = 8;
    __shared__ __align__(16) float tile[CH][18][34];
    __shared__ __align__(16) ull   wp[CH][9][8];
    __shared__ float ssc[16], sbi[16];
    __shared__ float pbuf[16][16][16];

    const int tpx = S / 32;                 // tiles per row (x direction)
    int tx = blockIdx.x % tpx, ty = blockIdx.x / tpx;
    int ocb = blockIdx.y * 16;
    int n   = blockIdx.z;
    int tid = threadIdx.x;
    int py = tid >> 4, hx = tid & 15;
    int x0 = 2 * hx;

    if (tid < 16) {
        int oc = ocb + tid;
        float s = g[oc] * rsqrtf(v[oc] + 1e-5f);
        ssc[tid] = s;
        sbi[tid] = (bias[oc] - m[oc]) * s + be[oc];
    }

    ull acc0[8], acc1[8];
#pragma unroll
    for (int p = 0; p < 8; p++) { acc0[p] = 0ULL; acc1[p] = 0ULL; }

    int oy0 = ty * 16, ox0 = tx * 32;
    for (int c0 = 0; c0 < CIN; c0 += CH) {
        // stage input tile (16+2 halo rows x 32+2 halo cols x CH channels)
        for (int i = tid; i < CH * 18 * 34; i += 256) {
            int c = i / 612, r = (i % 612) / 34, col = i % 34;
            int gy = oy0 - 1 + r, gx = ox0 - 1 + col;
            float val = 0.f;
            if (gy >= 0 && gy < S && gx >= 0 && gx < S)
                val = in[((n * CIN + c0 + c) * S + gy) * S + gx];
            tile[c][r][col] = val;
        }
        // stage weights, paired per 2 oc
        for (int i = tid; i < CH * 72; i += 256) {
            int p = i & 7, k = (i >> 3) % 9, c = i / 72;
            const float* wb = w + ((size_t)(ocb + 2 * p) * CIN + (c0 + c)) * 9 + k;
            wp[c][k][p] = pack2(wb[0], wb[(size_t)CIN * 9]);
        }
        __syncthreads();

#pragma unroll 2
        for (int c = 0; c < CH; c++) {
            float lv[3][4];
#pragma unroll
            for (int dy = 0; dy < 3; dy++) {
                float2 p01 = *(const float2*)&tile[c][py + dy][x0];
                float2 p23 = *(const float2*)&tile[c][py + dy][x0 + 2];
                lv[dy][0] = p01.x; lv[dy][1] = p01.y;
                lv[dy][2] = p23.x; lv[dy][3] = p23.y;
            }
#pragma unroll
            for (int k = 0; k < 9; k++) {
                int dy = k / 3, dx = k % 3;
                ull v0 = pack2(lv[dy][dx],     lv[dy][dx]);
                ull v1 = pack2(lv[dy][dx + 1], lv[dy][dx + 1]);
                const ulonglong2* wr = (const ulonglong2*)&wp[c][k][0];
#pragma unroll
                for (int p2 = 0; p2 < 4; p2++) {
                    ulonglong2 w2 = wr[p2];
                    acc0[2 * p2]     = fma2(v0, w2.x, acc0[2 * p2]);
                    acc0[2 * p2 + 1] = fma2(v0, w2.y, acc0[2 * p2 + 1]);
                    acc1[2 * p2]     = fma2(v1, w2.x, acc1[2 * p2]);
                    acc1[2 * p2 + 1] = fma2(v1, w2.y, acc1[2 * p2 + 1]);
                }
            }
        }
        __syncthreads();
    }

    // BN + ReLU + horizontal pool (in registers), stash h-pooled row
    float af0[16], af1[16];
#pragma unroll
    for (int p = 0; p < 8; p++) {
        unpack2(acc0[p], af0[2 * p], af0[2 * p + 1]);
        unpack2(acc1[p], af1[2 * p], af1[2 * p + 1]);
    }
#pragma unroll
    for (int j = 0; j < 16; j++) {
        float y0 = fmaxf(fmaf(af0[j], ssc[j], sbi[j]), 0.f);
        float y1 = fmaxf(fmaf(af1[j], ssc[j], sbi[j]), 0.f);
        pbuf[j][py][hx] = fmaxf(y0, y1);
    }
    __syncthreads();

    // vertical pool + write (16 oc x 8 rows x 16 cols = 2048 outputs)
    const int Sp = S / 2;
    for (int i = tid; i < 2048; i += 256) {
        int oc = i >> 7, rem = i & 127, pr = rem >> 4, pc = rem & 15;
        float vmax = fmaxf(pbuf[oc][2 * pr][pc], pbuf[oc][2 * pr + 1][pc]);
        out[((n * OCTOT + ocb + oc) * Sp + ty * 8 + pr) * Sp + tx * 16 + pc] = vmax;
    }
}

// ---------------------------------------------------------------------------
// ConvLSTM gate conv via 3xFP16 mma.sync GEMM.
// Grid: (8 mtiles, 4 = ntile+2*b, 4 ksplits), 256 threads (8 warps).
// ---------------------------------------------------------------------------
__global__ void __launch_bounds__(256) lstm_mma(
    const __half* __restrict__ wph, const __half* __restrict__ wpl,
    const __half* __restrict__ bxh_t, const __half* __restrict__ bxl_t)
{
    __shared__ __align__(16) __half Ah[2][128 * 24];
    __shared__ __align__(16) __half Al[2][128 * 24];
    __shared__ __align__(16) __half Bh[2][16 * 136];
    __shared__ __align__(16) __half Bl[2][16 * 136];

    int tid  = threadIdx.x;
    int lane = tid & 31;
    int wid  = tid >> 5;
    int wm = wid & 3, wn = wid >> 2;

    int mtile = blockIdx.x;
    int ntile = blockIdx.y & 1;
    int b     = blockIdx.y >> 1;
    int split = blockIdx.z;
    int ocb   = mtile * 128;

    const __half* bxh = bxh_t + (size_t)b * BHS;
    const __half* bxl = bxl_t + (size_t)b * BHS;
    const __half* bhh = g_bhh + (size_t)b * BHS;
    const __half* bhl = g_bhl + (size_t)b * BHS;

    int arow = tid >> 1, au = tid & 1;
    uint32_t ah_dst[2], al_dst[2], bh_dst[2], bl_dst[2];
    {
        uint32_t ao = arow * 48 + au * 16;
        int br_ = tid >> 4, bc_ = tid & 15;
        uint32_t bo = br_ * 272 + bc_ * 16;
        ah_dst[0] = smem_u32(&Ah[0][0]) + ao; ah_dst[1] = smem_u32(&Ah[1][0]) + ao;
        al_dst[0] = smem_u32(&Al[0][0]) + ao; al_dst[1] = smem_u32(&Al[1][0]) + ao;
        bh_dst[0] = smem_u32(&Bh[0][0]) + bo; bh_dst[1] = smem_u32(&Bh[1][0]) + bo;
        bl_dst[0] = smem_u32(&Bl[0][0]) + bo; bl_dst[1] = smem_u32(&Bl[1][0]) + bo;
    }
    size_t a_off_elem = (size_t)(arow + ocb) * 16 + au * 8;   // + G*16384
    int b_src_off = (tid >> 4) * 256 + ntile * 128 + (tid & 15) * 8;

    int quad = lane >> 3, l7 = lane & 7;
    uint32_t a_off[2], b_off[4];
    {
        int rsub = ((quad & 1) << 3) + l7;
        int ksub = (quad >> 1) << 4;
#pragma unroll
        for (int mi = 0; mi < 2; mi++)
            a_off[mi] = (uint32_t)((wm * 32 + mi * 16 + rsub) * 48 + ksub);
        int krow = ((quad & 1) << 3) + l7;
        int nsub = (quad >> 1) << 3;
#pragma unroll
        for (int ni2 = 0; ni2 < 4; ni2++)
            b_off[ni2] = (uint32_t)(krow * 272 + (wn * 64 + ni2 * 16 + nsub) * 2);
    }
    uint32_t ahb[2] = { smem_u32(&Ah[0][0]), smem_u32(&Ah[1][0]) };
    uint32_t alb[2] = { smem_u32(&Al[0][0]), smem_u32(&Al[1][0]) };
    uint32_t bhb[2] = { smem_u32(&Bh[0][0]), smem_u32(&Bh[1][0]) };
    uint32_t blb[2] = { smem_u32(&Bl[0][0]), smem_u32(&Bl[1][0]) };

    float acc[2][8][4];
#pragma unroll
    for (int mi = 0; mi < 2; mi++)
#pragma unroll
        for (int ni = 0; ni < 8; ni++)
#pragma unroll
            for (int q = 0; q < 4; q++) acc[mi][ni][q] = 0.f;

    auto stage = [&](int j, int buf) {
        int G  = split * 72 + j;
        int s  = G >> 5;
        int c0 = (G & 31) << 4;
        bool xh = (c0 < 256);
        size_t srow = ((size_t)(s * 256 + (xh ? c0 : c0 - 256)) << 8);
        const __half* bsh = (xh ? bxh : bhh) + srow;
        const __half* bsl = (xh ? bxl : bhl) + srow;
        cp16(ah_dst[buf], wph + (size_t)G * 16384 + a_off_elem);
        cp16(al_dst[buf], wpl + (size_t)G * 16384 + a_off_elem);
        cp16(bh_dst[buf], bsh + b_src_off);
        cp16(bl_dst[buf], bsl + b_src_off);
        cp_commit();
    };

    stage(0, 0);
    stage(1, 1);

    for (int j = 0; j < 72; j++) {
        if (j < 71) cp_wait<1>(); else cp_wait<0>();
        __syncthreads();

        int buf = j & 1;
        uint32_t ah[2][4], al[2][4], bh_[4][4], bl_[4][4];
#pragma unroll
        for (int mi = 0; mi < 2; mi++) {
            ldm_x4(ah[mi], ahb[buf] + a_off[mi]);
            ldm_x4(al[mi], alb[buf] + a_off[mi]);
        }
#pragma unroll
        for (int ni2 = 0; ni2 < 4; ni2++) {
            ldm_x4t(bh_[ni2], bhb[buf] + b_off[ni2]);
            ldm_x4t(bl_[ni2], blb[buf] + b_off[ni2]);
        }
#pragma unroll
        for (int mi = 0; mi < 2; mi++)
#pragma unroll
            for (int ni = 0; ni < 8; ni++) {
                const uint32_t* bhf = &bh_[ni >> 1][(ni & 1) * 2];
                const uint32_t* blf = &bl_[ni >> 1][(ni & 1) * 2];
                mma16816(acc[mi][ni], ah[mi], bhf);
                mma16816(acc[mi][ni], ah[mi], blf);
                mma16816(acc[mi][ni], al[mi], bhf);
            }

        __syncthreads();
        if (j + 2 < 72) stage(j + 2, buf);
    }

    int gq = lane >> 2, tq = lane & 3;
    float* zbase = g_zp + ((size_t)(split * 2 + b) * 1024) * 256;
    int row0 = ocb + wm * 32 + gq;
    int col0 = ntile * 128 + wn * 64 + 2 * tq;
#pragma unroll
    for (int mi = 0; mi < 2; mi++)
#pragma unroll
        for (int ni = 0; ni < 8; ni++) {
            int r = row0 + mi * 16;
            int cc = col0 + ni * 8;
            *(float2*)(zbase + (size_t)r * 256 + cc)       = make_float2(acc[mi][ni][0], acc[mi][ni][1]);
            *(float2*)(zbase + (size_t)(r + 8) * 256 + cc) = make_float2(acc[mi][ni][2], acc[mi][ni][3]);
        }
}

// ---------------------------------------------------------------------------
// Gates: sum 4 K-split partials + bias, nonlinearities, state update,
// scatter h (hi/lo) into im2col buffers (bh always; bx1 when layer 0).
// ---------------------------------------------------------------------------
__global__ void __launch_bounds__(256) lstm_gates(int t, int layer,
                                                  const float* __restrict__ lb,
                                                  float* __restrict__ out)
{
    int idx = blockIdx.x * 256 + threadIdx.x;  // 131072
    int inner = idx & 65535;
    int b = idx >> 16;
    int c = inner >> 8;
    int pos = inner & 255;

    float zi = lb[c], zf = lb[c + 256], zo = lb[c + 512], zg = lb[c + 768];
#pragma unroll
    for (int s = 0; s < 4; s++) {
        const float* zb = g_zp + ((size_t)s * 2 + b) * 1024 * 256;
        zi += zb[(size_t)(c)       * 256 + pos];
        zf += zb[(size_t)(c + 256) * 256 + pos];
        zo += zb[(size_t)(c + 512) * 256 + pos];
        zg += zb[(size_t)(c + 768) * 256 + pos];
    }

    float cn = sigmoidf_(zf) * g_c[idx] + sigmoidf_(zi) * tanhf(zg);
    float hn = sigmoidf_(zo) * tanhf(cn);
    g_c[idx] = cn;

    __half hh = __float2half(hn);
    __half hl = __float2half(hn - __half2float(hh));
    int y = pos >> 4, x = pos & 15;
    __half* bhhp = g_bhh + (size_t)b * BHS;
    __half* bhlp = g_bhl + (size_t)b * BHS;
    __half* bxhp = g_bx1h + (size_t)(t * 2 + b) * BHS;
    __half* bxlp = g_bx1l + (size_t)(t * 2 + b) * BHS;
#pragma unroll
    for (int s = 0; s < 9; s++) {
        int dy = s / 3 - 1, dx = s % 3 - 1;
        int ny = y - dy, nx = x - dx;
        if (ny >= 0 && ny < 16 && nx >= 0 && nx < 16) {
            int o = ((s * 256 + c) << 8) + ny * 16 + nx;
            bhhp[o] = hh;
            bhlp[o] = hl;
            if (layer == 0) { bxhp[o] = hh; bxlp[o] = hl; }
        }
    }

    if (layer == 1)
        out[(size_t)b * 16 * CHW2 + (size_t)t * CHW2 + inner] = hn;
}

// zero c state and h im2col buffers
__global__ void __launch_bounds__(256) zero_state()
{
    int idx = blockIdx.x * 256 + threadIdx.x;   // 1179648
    if (idx < 131072) g_c[idx] = 0.f;
    g_bhh[idx] = __float2half(0.f);
    g_bhl[idx] = __float2half(0.f);
}

__global__ void __launch_bounds__(256) copy_last(float* __restrict__ out)
{
    int idx = blockIdx.x * 256 + threadIdx.x;   // 131072
    int inner = idx & 65535;
    int b = idx >> 16;
    out[2097152 + idx] = out[(size_t)b * 16 * CHW2 + 15 * CHW2 + inner];
}

// ---------------------------------------------------------------------------
// Launch sequence (graph-capturable)
// ---------------------------------------------------------------------------
extern "C" void kernel_launch(void* const* d_in, const int* in_sizes, int n_in,
                              void* d_out, int out_size)
{
    const float* x   = (const float*)d_in[0];
    const float* w0  = (const float*)d_in[1];
    const float* b0  = (const float*)d_in[2];
    const float* g0  = (const float*)d_in[3];
    const float* be0 = (const float*)d_in[4];
    const float* m0  = (const float*)d_in[5];
    const float* v0  = (const float*)d_in[6];
    const float* w1  = (const float*)d_in[7];
    const float* b1  = (const float*)d_in[8];
    const float* g1  = (const float*)d_in[9];
    const float* be1 = (const float*)d_in[10];
    const float* m1  = (const float*)d_in[11];
    const float* v1  = (const float*)d_in[12];
    const float* w2  = (const float*)d_in[13];
    const float* b2  = (const float*)d_in[14];
    const float* g2  = (const float*)d_in[15];
    const float* be2 = (const float*)d_in[16];
    const float* m2  = (const float*)d_in[17];
    const float* v2  = (const float*)d_in[18];
    const float* lw0 = (const float*)d_in[19];
    const float* lb0 = (const float*)d_in[20];
    const float* lw1 = (const float*)d_in[21];
    const float* lb1 = (const float*)d_in[22];
    float* out = (float*)d_out;

    float* f0ptr; cudaGetSymbolAddress((void**)&f0ptr, g_f0);
    float* f1ptr; cudaGetSymbolAddress((void**)&f1ptr, g_f1);
    float* f2ptr; cudaGetSymbolAddress((void**)&f2ptr, g_f2);
    __half* wphptr; cudaGetSymbolAddress((void**)&wphptr, g_wph);
    __half* wplptr; cudaGetSymbolAddress((void**)&wplptr, g_wpl);
    __half* bx0hptr; cudaGetSymbolAddress((void**)&bx0hptr, g_bx0h);
    __half* bx0lptr; cudaGetSymbolAddress((void**)&bx0lptr, g_bx0l);
    __half* bx1hptr; cudaGetSymbolAddress((void**)&bx1hptr, g_bx1h);
    __half* bx1lptr; cudaGetSymbolAddress((void**)&bx1lptr, g_bx1l);

    // weight prepack (hi/lo fp16, chunk-major layout)
    prepack_w<<<18432, 256>>>(lw0, 0);
    prepack_w<<<18432, 256>>>(lw1, 1);

    // CNN encoder over all 32 frames
    conv0_pool<<<32768, 256>>>(x, w0, b0, g0, be0, m0, v0);
    // block1: tiles (2x in x, 4 in y) = 8, 8 oc-groups, 32 frames
    cnn_conv_pool<64, 64, 128><<<dim3(8, 8, 32), 256>>>(f0ptr, w1, b1, g1, be1, m1, v1, f1ptr);
    // block2: tiles (1x, 2y) = 2, 16 oc-groups, 32 frames
    cnn_conv_pool<128, 32, 256><<<dim3(2, 16, 32), 256>>>(f1ptr, w2, b2, g2, be2, m2, v2, f2ptr);

    // hi/lo fp16 im2col of CNN features: 32*BHS / 256 = 73728 blocks
    build_bx0<<<73728, 256>>>();

    // ConvLSTM layer 0
    zero_state<<<4608, 256>>>();
    for (int t = 0; t < 16; t++) {
        lstm_mma<<<dim3(8, 4, 4), 256>>>(wphptr, wplptr,
                                         bx0hptr + (size_t)t * 2 * BHS,
                                         bx0lptr + (size_t)t * 2 * BHS);
        lstm_gates<<<512, 256>>>(t, 0, lb0, out);
    }

    // ConvLSTM layer 1
    zero_state<<<4608, 256>>>();
    for (int t = 0; t < 16; t++) {
        lstm_mma<<<dim3(8, 4, 4), 256>>>(wphptr + (size_t)288 * 1024 * 16,
                                         wplptr + (size_t)288 * 1024 * 16,
                                         bx1hptr + (size_t)t * 2 * BHS,
                                         bx1lptr + (size_t)t * 2 * BHS);
        lstm_gates<<<512, 256>>>(t, 1, lb1, out);
    }

    copy_last<<<512, 256>>>(out);
}

// round 8
// speedup vs baseline: 5.2368x; 1.2246x over previous
#include <cuda_runtime.h>
#include <cuda_fp16.h>
#include <math.h>
#include <stdint.h>

// ---------------------------------------------------------------------------
//   x: (2,16,1,128,128)
//   block0: 1->64,  128x128 -> pool -> 64x64   (SIMT)
//   block1: 64->128, 64x64  -> pool -> 32x32   (3xFP16 MMA GEMM)
//   block2: 128->256,32x32  -> pool -> 16x16   (3xFP16 MMA GEMM)
//   ConvLSTM x2: cin=512, cout=1024, 3x3, 16x16 (3xFP16 MMA GEMM)
//   out: z_seq (2,16,256,16,16) ++ z_last (2,256,16,16)
// All conv-as-GEMM: k = s*CIN + c, s=(dy+1)*3+(dx+1)
// 3xFP16 error-compensated mma.sync:  D += Ah*Bh + Ah*Bl + Al*Bh
// ---------------------------------------------------------------------------

#define CHW2 65536          // 256*16*16
#define BHS  589824         // 9*256*256

typedef unsigned long long ull;

// ============================ PTX helpers ==================================
__device__ __forceinline__ uint32_t smem_u32(const void* p) {
    uint32_t a;
    asm("{ .reg .u64 t; cvta.to.shared.u64 t, %1; cvt.u32.u64 %0, t; }" : "=r"(a) : "l"(p));
    return a;
}
__device__ __forceinline__ void ldm_x4(uint32_t* r, uint32_t addr) {
    asm volatile("ldmatrix.sync.aligned.m8n8.x4.shared.b16 {%0,%1,%2,%3}, [%4];"
        : "=r"(r[0]), "=r"(r[1]), "=r"(r[2]), "=r"(r[3]) : "r"(addr));
}
__device__ __forceinline__ void ldm_x4t(uint32_t* r, uint32_t addr) {
    asm volatile("ldmatrix.sync.aligned.m8n8.x4.trans.shared.b16 {%0,%1,%2,%3}, [%4];"
        : "=r"(r[0]), "=r"(r[1]), "=r"(r[2]), "=r"(r[3]) : "r"(addr));
}
__device__ __forceinline__ void mma16816(float* d, const uint32_t* a, const uint32_t* b) {
    asm volatile(
        "mma.sync.aligned.m16n8k16.row.col.f32.f16.f16.f32 "
        "{%0,%1,%2,%3}, {%4,%5,%6,%7}, {%8,%9}, {%0,%1,%2,%3};"
        : "+f"(d[0]), "+f"(d[1]), "+f"(d[2]), "+f"(d[3])
        : "r"(a[0]), "r"(a[1]), "r"(a[2]), "r"(a[3]), "r"(b[0]), "r"(b[1]));
}
__device__ __forceinline__ void cp16(uint32_t sdst, const void* gsrc) {
    asm volatile("cp.async.cg.shared.global [%0], [%1], 16;" :: "r"(sdst), "l"(gsrc));
}
__device__ __forceinline__ void cp_commit() { asm volatile("cp.async.commit_group;"); }
template <int N> __device__ __forceinline__ void cp_wait() {
    asm volatile("cp.async.wait_group %0;" :: "n"(N));
}
__device__ __forceinline__ float sigmoidf_(float x) { return 1.0f / (1.0f + expf(-x)); }

// ---------------------------------------------------------------------------
// Scratch
// ---------------------------------------------------------------------------
__device__ __align__(256) float  g_f0[32 * 64 * 64 * 64];
__device__ __align__(256) float  g_f1[32 * 128 * 32 * 32];
__device__ __align__(256) float  g_f2[32 * 256 * 16 * 16];
__device__ __align__(256) float  g_pre[32 * 128 * 64 * 64];   // pre-pool conv output (reused)
__device__ __align__(256) __half g_wc1h[36 * 128 * 16];       // block1 weights hi [G][oc][16]
__device__ __align__(256) __half g_wc1l[36 * 128 * 16];
__device__ __align__(256) __half g_wc2h[72 * 256 * 16];       // block2 weights
__device__ __align__(256) __half g_wc2l[72 * 256 * 16];
__device__ __align__(256) __half g_wph[2 * 288 * 1024 * 16];  // lstm weights hi
__device__ __align__(256) __half g_wpl[2 * 288 * 1024 * 16];
__device__ __align__(256) __half g_bx0h[32 * BHS];
__device__ __align__(256) __half g_bx0l[32 * BHS];
__device__ __align__(256) __half g_bx1h[32 * BHS];
__device__ __align__(256) __half g_bx1l[32 * BHS];
__device__ __align__(256) __half g_bhh[2 * BHS];
__device__ __align__(256) __half g_bhl[2 * BHS];
__device__ __align__(256) float  g_c[2 * 256 * 16 * 16];
__device__ __align__(256) float  g_zp[4 * 2 * 1024 * 256];

// ---------------------------------------------------------------------------
// LSTM weight prepack: fp32 -> (hi, lo) fp16 in [layer][G][oc][16]
// ---------------------------------------------------------------------------
__global__ void __launch_bounds__(256) prepack_w(const float* __restrict__ lw, int layer)
{
    int idx = blockIdx.x * 256 + threadIdx.x;  // 4718592
    int u  = idx & 15;
    int oc = (idx >> 4) & 1023;
    int G  = idx >> 14;
    int k  = G * 16 + u;
    int s  = k >> 9;
    int c  = k & 511;
    float w = lw[((size_t)oc * 512 + c) * 9 + s];
    __half hi = __float2half(w);
    size_t o = (size_t)layer * 4718592 + idx;
    g_wph[o] = hi;
    g_wpl[o] = __float2half(w - __half2float(hi));
}

// ---------------------------------------------------------------------------
// CNN conv weight prepack: w[oc][c][ky][kx] -> [G][oc][16] hi/lo, k=s*CIN+c
// ---------------------------------------------------------------------------
template <int CIN, int OCTOT>
__global__ void __launch_bounds__(256) prepack_cw(
    const float* __restrict__ w, __half* __restrict__ outh, __half* __restrict__ outl)
{
    constexpr int CPG = CIN / 16;
    int idx = blockIdx.x * 256 + threadIdx.x;  // NG*OCTOT*16
    int u  = idx & 15;
    int oc = (idx >> 4) % OCTOT;
    int G  = (idx >> 4) / OCTOT;
    int s  = G / CPG;
    int c  = (G % CPG) * 16 + u;
    float val = w[((size_t)oc * CIN + c) * 9 + s];
    __half hi = __float2half(val);
    outh[idx] = hi;
    outl[idx] = __float2half(val - __half2float(hi));
}

// ---------------------------------------------------------------------------
// Build layer0 x im2col (hi/lo) from CNN features. 32*BHS elements.
// ---------------------------------------------------------------------------
__global__ void __launch_bounds__(256) build_bx0()
{
    int idx = blockIdx.x * 256 + threadIdx.x;   // < 18874368
    int n   = idx & 255;
    int c   = (idx >> 8) & 255;
    int rem = idx >> 16;
    int s   = rem % 9;
    int tb  = rem / 9;
    int t   = tb >> 1, b = tb & 1;
    int dy  = s / 3 - 1, dx = s % 3 - 1;
    int iy  = (n >> 4) + dy, ix = (n & 15) + dx;
    float val = 0.f;
    if (iy >= 0 && iy < 16 && ix >= 0 && ix < 16)
        val = g_f2[(((size_t)(b * 16 + t) * 256 + c) << 8) + iy * 16 + ix];
    __half hi = __float2half(val);
    g_bx0h[idx] = hi;
    g_bx0l[idx] = __float2half(val - __half2float(hi));
}

// ---------------------------------------------------------------------------
// Block 0: 1 input channel. One thread per pooled output.
// ---------------------------------------------------------------------------
__global__ void __launch_bounds__(256) conv0_pool(
    const float* __restrict__ x, const float* __restrict__ w,
    const float* __restrict__ bias, const float* __restrict__ g,
    const float* __restrict__ be, const float* __restrict__ m,
    const float* __restrict__ v)
{
    int idx = blockIdx.x * 256 + threadIdx.x;   // 8388608
    int pw = idx & 63;
    int ph = (idx >> 6) & 63;
    int oc = (idx >> 12) & 63;
    int n  = idx >> 18;

    float wr[9];
#pragma unroll
    for (int k = 0; k < 9; k++) wr[k] = w[oc * 9 + k];
    float s  = g[oc] * rsqrtf(v[oc] + 1e-5f);
    float cb = (bias[oc] - m[oc]) * s + be[oc];

    const float* xi = x + n * 16384;
    float mx = -1e30f;
#pragma unroll
    for (int dy0 = 0; dy0 < 2; dy0++) {
#pragma unroll
        for (int dx0 = 0; dx0 < 2; dx0++) {
            int oy = 2 * ph + dy0, ox = 2 * pw + dx0;
            float sum = 0.f;
#pragma unroll
            for (int ky = 0; ky < 3; ky++) {
                int iy = oy - 1 + ky;
                if (iy < 0 || iy >= 128) continue;
#pragma unroll
                for (int kx = 0; kx < 3; kx++) {
                    int ix = ox - 1 + kx;
                    if (ix < 0 || ix >= 128) continue;
                    sum = fmaf(xi[iy * 128 + ix], wr[ky * 3 + kx], sum);
                }
            }
            float y = fmaxf(fmaf(sum, s, cb), 0.f);
            mx = fmaxf(mx, y);
        }
    }
    g_f0[idx] = mx;
}

// ---------------------------------------------------------------------------
// CNN conv via 3xFP16 mma.sync GEMM, on-the-fly shifted im2col.
// CTA tile M=128 (oc), N=128 (positions), K=9*CIN. 256 threads, 8 warps.
// B chunk staged from fp32 feature map with bounds mask, hi/lo split.
// Epilogue: BN+ReLU -> pre-pool fp32 buffer.
// ---------------------------------------------------------------------------
template <int CIN, int S, int OCTOT>
__global__ void __launch_bounds__(256) conv_mma(
    const float* __restrict__ in,
    const __half* __restrict__ wph, const __half* __restrict__ wpl,
    const float* __restrict__ bias, const float* __restrict__ g,
    const float* __restrict__ be, const float* __restrict__ m,
    const float* __restrict__ v, float* __restrict__ pre)
{
    constexpr int NPOS = S * S;
    constexpr int CPG  = CIN / 16;
    constexpr int NG   = 9 * CPG;
    constexpr int LOGS = (S == 64) ? 6 : 5;

    __shared__ __align__(16) __half Ah[2][128 * 24];
    __shared__ __align__(16) __half Al[2][128 * 24];
    __shared__ __align__(16) __half Bh[2][16 * 136];
    __shared__ __align__(16) __half Bl[2][16 * 136];
    __shared__ float ssc[128], sbi[128];

    int tid = threadIdx.x, lane = tid & 31, wid = tid >> 5;
    int wm = wid & 3, wn = wid >> 2;
    int ntile = blockIdx.x;
    int ocb   = blockIdx.y * 128;
    int frame = blockIdx.z;

    if (tid < 128) {
        int oc = ocb + tid;
        float s_ = g[oc] * rsqrtf(v[oc] + 1e-5f);
        ssc[tid] = s_;
        sbi[tid] = (bias[oc] - m[oc]) * s_ + be[oc];
    }

    // A staging (cp.async)
    int arow = tid >> 1, au = tid & 1;
    uint32_t ao = arow * 48 + au * 16;
    uint32_t ah_dst[2] = { smem_u32(&Ah[0][0]) + ao, smem_u32(&Ah[1][0]) + ao };
    uint32_t al_dst[2] = { smem_u32(&Al[0][0]) + ao, smem_u32(&Al[1][0]) + ao };
    size_t a_off_elem = (size_t)(ocb + arow) * 16 + au * 8;

    // B staging (LDG->reg->cvt->STS)
    int bk = tid >> 4, bn = tid & 15;
    int nbase = ntile * 128 + bn * 8;

    float breg[8];
    auto prefetchB = [&](int G) {
        int s = G / CPG, q = G - s * CPG;
        int dy = s / 3 - 1, dx = s % 3 - 1;
        const float* src = in + ((size_t)frame * CIN + q * 16 + bk) * NPOS;
#pragma unroll
        for (int j = 0; j < 8; j++) {
            int pos = nbase + j;
            int y = pos >> LOGS, x = pos & (S - 1);
            int iy = y + dy, ix = x + dx;
            breg[j] = (iy >= 0 && iy < S && ix >= 0 && ix < S) ? src[iy * S + ix] : 0.f;
        }
    };
    auto stsB = [&](int buf) {
        __half hv[8], lv[8];
#pragma unroll
        for (int j = 0; j < 8; j++) {
            hv[j] = __float2half(breg[j]);
            lv[j] = __float2half(breg[j] - __half2float(hv[j]));
        }
        *(uint4*)&Bh[buf][bk * 136 + bn * 8] = *(uint4*)hv;
        *(uint4*)&Bl[buf][bk * 136 + bn * 8] = *(uint4*)lv;
    };
    auto cpA = [&](int G, int buf) {
        cp16(ah_dst[buf], wph + (size_t)G * (OCTOT * 16) + a_off_elem);
        cp16(al_dst[buf], wpl + (size_t)G * (OCTOT * 16) + a_off_elem);
        cp_commit();
    };

    // ldmatrix lane offsets
    int quad = lane >> 3, l7 = lane & 7;
    uint32_t a_off[2], b_off[4];
    {
        int rsub = ((quad & 1) << 3) + l7;
        int ksub = (quad >> 1) << 4;
#pragma unroll
        for (int mi = 0; mi < 2; mi++)
            a_off[mi] = (uint32_t)((wm * 32 + mi * 16 + rsub) * 48 + ksub);
        int krow = ((quad & 1) << 3) + l7;
        int nsub = (quad >> 1) << 3;
#pragma unroll
        for (int ni2 = 0; ni2 < 4; ni2++)
            b_off[ni2] = (uint32_t)(krow * 272 + (wn * 64 + ni2 * 16 + nsub) * 2);
    }
    uint32_t ahb[2] = { smem_u32(&Ah[0][0]), smem_u32(&Ah[1][0]) };
    uint32_t alb[2] = { smem_u32(&Al[0][0]), smem_u32(&Al[1][0]) };
    uint32_t bhb[2] = { smem_u32(&Bh[0][0]), smem_u32(&Bh[1][0]) };
    uint32_t blb[2] = { smem_u32(&Bl[0][0]), smem_u32(&Bl[1][0]) };

    float acc[2][8][4];
#pragma unroll
    for (int mi = 0; mi < 2; mi++)
#pragma unroll
        for (int ni = 0; ni < 8; ni++)
#pragma unroll
            for (int q = 0; q < 4; q++) acc[mi][ni][q] = 0.f;

    prefetchB(0); stsB(0); cpA(0, 0);
    prefetchB(1); stsB(1); cpA(1, 1);
    if (NG > 2) prefetchB(2);

    for (int j = 0; j < NG; j++) {
        if (j < NG - 1) cp_wait<1>(); else cp_wait<0>();
        __syncthreads();

        int buf = j & 1;
        uint32_t ah[2][4], al[2][4], bh_[4][4], bl_[4][4];
#pragma unroll
        for (int mi = 0; mi < 2; mi++) {
            ldm_x4(ah[mi], ahb[buf] + a_off[mi]);
            ldm_x4(al[mi], alb[buf] + a_off[mi]);
        }
#pragma unroll
        for (int ni2 = 0; ni2 < 4; ni2++) {
            ldm_x4t(bh_[ni2], bhb[buf] + b_off[ni2]);
            ldm_x4t(bl_[ni2], blb[buf] + b_off[ni2]);
        }
#pragma unroll
        for (int mi = 0; mi < 2; mi++)
#pragma unroll
            for (int ni = 0; ni < 8; ni++) {
                const uint32_t* bhf = &bh_[ni >> 1][(ni & 1) * 2];
                const uint32_t* blf = &bl_[ni >> 1][(ni & 1) * 2];
                mma16816(acc[mi][ni], ah[mi], bhf);
                mma16816(acc[mi][ni], ah[mi], blf);
                mma16816(acc[mi][ni], al[mi], bhf);
            }
        __syncthreads();

        if (j + 2 < NG) {
            stsB(buf);            // breg holds chunk j+2
            cpA(j + 2, buf);
            if (j + 3 < NG) prefetchB(j + 3);
        }
    }

    // Epilogue: BN + ReLU -> pre-pool buffer
    int gq = lane >> 2, tq = lane & 3;
    int row0 = wm * 32 + gq;                  // local oc
    int colb = ntile * 128 + wn * 64 + 2 * tq;
#pragma unroll
    for (int mi = 0; mi < 2; mi++)
#pragma unroll
        for (int ni = 0; ni < 8; ni++) {
            int r0 = row0 + mi * 16;
            int col = colb + ni * 8;
#pragma unroll
            for (int h = 0; h < 2; h++) {
                int r = r0 + h * 8;
                float sc = ssc[r], sh = sbi[r];
                float v0 = fmaxf(fmaf(acc[mi][ni][2 * h],     sc, sh), 0.f);
                float v1 = fmaxf(fmaf(acc[mi][ni][2 * h + 1], sc, sh), 0.f);
                *(float2*)(pre + ((size_t)frame * OCTOT + ocb + r) * NPOS + col)
                    = make_float2(v0, v1);
            }
        }
}

// ---------------------------------------------------------------------------
// 2x2 maxpool: pre [32][OC][S][S] -> out [32][OC][S/2][S/2]
// ---------------------------------------------------------------------------
template <int OC, int S>
__global__ void __launch_bounds__(256) pool2(const float* __restrict__ pre,
                                             float* __restrict__ out)
{
    constexpr int HP = S / 2;
    int idx = blockIdx.x * 256 + threadIdx.x;   // 32*OC*HP*HP
    int pw = idx % HP;
    int t1 = idx / HP;
    int ph = t1 % HP;
    int t2 = t1 / HP;                           // n*OC + oc
    const float* p = pre + (size_t)t2 * S * S + (2 * ph) * S + 2 * pw;
    float a = p[0], b = p[1], c = p[S], d = p[S + 1];
    out[idx] = fmaxf(fmaxf(a, b), fmaxf(c, d));
}

// ---------------------------------------------------------------------------
// ConvLSTM gate conv via 3xFP16 mma.sync GEMM (unchanged).
// ---------------------------------------------------------------------------
__global__ void __launch_bounds__(256) lstm_mma(
    const __half* __restrict__ wph, const __half* __restrict__ wpl,
    const __half* __restrict__ bxh_t, const __half* __restrict__ bxl_t)
{
    __shared__ __align__(16) __half Ah[2][128 * 24];
    __shared__ __align__(16) __half Al[2][128 * 24];
    __shared__ __align__(16) __half Bh[2][16 * 136];
    __shared__ __align__(16) __half Bl[2][16 * 136];

    int tid  = threadIdx.x;
    int lane = tid & 31;
    int wid  = tid >> 5;
    int wm = wid & 3, wn = wid >> 2;

    int mtile = blockIdx.x;
    int ntile = blockIdx.y & 1;
    int b     = blockIdx.y >> 1;
    int split = blockIdx.z;
    int ocb   = mtile * 128;

    const __half* bxh = bxh_t + (size_t)b * BHS;
    const __half* bxl = bxl_t + (size_t)b * BHS;
    const __half* bhh = g_bhh + (size_t)b * BHS;
    const __half* bhl = g_bhl + (size_t)b * BHS;

    int arow = tid >> 1, au = tid & 1;
    uint32_t ah_dst[2], al_dst[2], bh_dst[2], bl_dst[2];
    {
        uint32_t ao = arow * 48 + au * 16;
        int br_ = tid >> 4, bc_ = tid & 15;
        uint32_t bo = br_ * 272 + bc_ * 16;
        ah_dst[0] = smem_u32(&Ah[0][0]) + ao; ah_dst[1] = smem_u32(&Ah[1][0]) + ao;
        al_dst[0] = smem_u32(&Al[0][0]) + ao; al_dst[1] = smem_u32(&Al[1][0]) + ao;
        bh_dst[0] = smem_u32(&Bh[0][0]) + bo; bh_dst[1] = smem_u32(&Bh[1][0]) + bo;
        bl_dst[0] = smem_u32(&Bl[0][0]) + bo; bl_dst[1] = smem_u32(&Bl[1][0]) + bo;
    }
    size_t a_off_elem = (size_t)(arow + ocb) * 16 + au * 8;
    int b_src_off = (tid >> 4) * 256 + ntile * 128 + (tid & 15) * 8;

    int quad = lane >> 3, l7 = lane & 7;
    uint32_t a_off[2], b_off[4];
    {
        int rsub = ((quad & 1) << 3) + l7;
        int ksub = (quad >> 1) << 4;
#pragma unroll
        for (int mi = 0; mi < 2; mi++)
            a_off[mi] = (uint32_t)((wm * 32 + mi * 16 + rsub) * 48 + ksub);
        int krow = ((quad & 1) << 3) + l7;
        int nsub = (quad >> 1) << 3;
#pragma unroll
        for (int ni2 = 0; ni2 < 4; ni2++)
            b_off[ni2] = (uint32_t)(krow * 272 + (wn * 64 + ni2 * 16 + nsub) * 2);
    }
    uint32_t ahb[2] = { smem_u32(&Ah[0][0]), smem_u32(&Ah[1][0]) };
    uint32_t alb[2] = { smem_u32(&Al[0][0]), smem_u32(&Al[1][0]) };
    uint32_t bhb[2] = { smem_u32(&Bh[0][0]), smem_u32(&Bh[1][0]) };
    uint32_t blb[2] = { smem_u32(&Bl[0][0]), smem_u32(&Bl[1][0]) };

    float acc[2][8][4];
#pragma unroll
    for (int mi = 0; mi < 2; mi++)
#pragma unroll
        for (int ni = 0; ni < 8; ni++)
#pragma unroll
            for (int q = 0; q < 4; q++) acc[mi][ni][q] = 0.f;

    auto stage = [&](int j, int buf) {
        int G  = split * 72 + j;
        int s  = G >> 5;
        int c0 = (G & 31) << 4;
        bool xh = (c0 < 256);
        size_t srow = ((size_t)(s * 256 + (xh ? c0 : c0 - 256)) << 8);
        const __half* bsh = (xh ? bxh : bhh) + srow;
        const __half* bsl = (xh ? bxl : bhl) + srow;
        cp16(ah_dst[buf], wph + (size_t)G * 16384 + a_off_elem);
        cp16(al_dst[buf], wpl + (size_t)G * 16384 + a_off_elem);
        cp16(bh_dst[buf], bsh + b_src_off);
        cp16(bl_dst[buf], bsl + b_src_off);
        cp_commit();
    };

    stage(0, 0);
    stage(1, 1);

    for (int j = 0; j < 72; j++) {
        if (j < 71) cp_wait<1>(); else cp_wait<0>();
        __syncthreads();

        int buf = j & 1;
        uint32_t ah[2][4], al[2][4], bh_[4][4], bl_[4][4];
#pragma unroll
        for (int mi = 0; mi < 2; mi++) {
            ldm_x4(ah[mi], ahb[buf] + a_off[mi]);
            ldm_x4(al[mi], alb[buf] + a_off[mi]);
        }
#pragma unroll
        for (int ni2 = 0; ni2 < 4; ni2++) {
            ldm_x4t(bh_[ni2], bhb[buf] + b_off[ni2]);
            ldm_x4t(bl_[ni2], blb[buf] + b_off[ni2]);
        }
#pragma unroll
        for (int mi = 0; mi < 2; mi++)
#pragma unroll
            for (int ni = 0; ni < 8; ni++) {
                const uint32_t* bhf = &bh_[ni >> 1][(ni & 1) * 2];
                const uint32_t* blf = &bl_[ni >> 1][(ni & 1) * 2];
                mma16816(acc[mi][ni], ah[mi], bhf);
                mma16816(acc[mi][ni], ah[mi], blf);
                mma16816(acc[mi][ni], al[mi], bhf);
            }

        __syncthreads();
        if (j + 2 < 72) stage(j + 2, buf);
    }

    int gq = lane >> 2, tq = lane & 3;
    float* zbase = g_zp + ((size_t)(split * 2 + b) * 1024) * 256;
    int row0 = ocb + wm * 32 + gq;
    int col0 = ntile * 128 + wn * 64 + 2 * tq;
#pragma unroll
    for (int mi = 0; mi < 2; mi++)
#pragma unroll
        for (int ni = 0; ni < 8; ni++) {
            int r = row0 + mi * 16;
            int cc = col0 + ni * 8;
            *(float2*)(zbase + (size_t)r * 256 + cc)       = make_float2(acc[mi][ni][0], acc[mi][ni][1]);
            *(float2*)(zbase + (size_t)(r + 8) * 256 + cc) = make_float2(acc[mi][ni][2], acc[mi][ni][3]);
        }
}

// ---------------------------------------------------------------------------
// Gates (unchanged)
// ---------------------------------------------------------------------------
__global__ void __launch_bounds__(256) lstm_gates(int t, int layer,
                                                  const float* __restrict__ lb,
                                                  float* __restrict__ out)
{
    int idx = blockIdx.x * 256 + threadIdx.x;  // 131072
    int inner = idx & 65535;
    int b = idx >> 16;
    int c = inner >> 8;
    int pos = inner & 255;

    float zi = lb[c], zf = lb[c + 256], zo = lb[c + 512], zg = lb[c + 768];
#pragma unroll
    for (int s = 0; s < 4; s++) {
        const float* zb = g_zp + ((size_t)s * 2 + b) * 1024 * 256;
        zi += zb[(size_t)(c)       * 256 + pos];
        zf += zb[(size_t)(c + 256) * 256 + pos];
        zo += zb[(size_t)(c + 512) * 256 + pos];
        zg += zb[(size_t)(c + 768) * 256 + pos];
    }

    float cn = sigmoidf_(zf) * g_c[idx] + sigmoidf_(zi) * tanhf(zg);
    float hn = sigmoidf_(zo) * tanhf(cn);
    g_c[idx] = cn;

    __half hh = __float2half(hn);
    __half hl = __float2half(hn - __half2float(hh));
    int y = pos >> 4, x = pos & 15;
    __half* bhhp = g_bhh + (size_t)b * BHS;
    __half* bhlp = g_bhl + (size_t)b * BHS;
    __half* bxhp = g_bx1h + (size_t)(t * 2 + b) * BHS;
    __half* bxlp = g_bx1l + (size_t)(t * 2 + b) * BHS;
#pragma unroll
    for (int s = 0; s < 9; s++) {
        int dy = s / 3 - 1, dx = s % 3 - 1;
        int ny = y - dy, nx = x - dx;
        if (ny >= 0 && ny < 16 && nx >= 0 && nx < 16) {
            int o = ((s * 256 + c) << 8) + ny * 16 + nx;
            bhhp[o] = hh;
            bhlp[o] = hl;
            if (layer == 0) { bxhp[o] = hh; bxlp[o] = hl; }
        }
    }

    if (layer == 1)
        out[(size_t)b * 16 * CHW2 + (size_t)t * CHW2 + inner] = hn;
}

__global__ void __launch_bounds__(256) zero_state()
{
    int idx = blockIdx.x * 256 + threadIdx.x;   // 1179648
    if (idx < 131072) g_c[idx] = 0.f;
    g_bhh[idx] = __float2half(0.f);
    g_bhl[idx] = __float2half(0.f);
}

__global__ void __launch_bounds__(256) copy_last(float* __restrict__ out)
{
    int idx = blockIdx.x * 256 + threadIdx.x;   // 131072
    int inner = idx & 65535;
    int b = idx >> 16;
    out[2097152 + idx] = out[(size_t)b * 16 * CHW2 + 15 * CHW2 + inner];
}

// ---------------------------------------------------------------------------
// Launch sequence (graph-capturable)
// ---------------------------------------------------------------------------
extern "C" void kernel_launch(void* const* d_in, const int* in_sizes, int n_in,
                              void* d_out, int out_size)
{
    const float* x   = (const float*)d_in[0];
    const float* w0  = (const float*)d_in[1];
    const float* b0  = (const float*)d_in[2];
    const float* g0  = (const float*)d_in[3];
    const float* be0 = (const float*)d_in[4];
    const float* m0  = (const float*)d_in[5];
    const float* v0  = (const float*)d_in[6];
    const float* w1  = (const float*)d_in[7];
    const float* b1  = (const float*)d_in[8];
    const float* g1  = (const float*)d_in[9];
    const float* be1 = (const float*)d_in[10];
    const float* m1  = (const float*)d_in[11];
    const float* v1  = (const float*)d_in[12];
    const float* w2  = (const float*)d_in[13];
    const float* b2  = (const float*)d_in[14];
    const float* g2  = (const float*)d_in[15];
    const float* be2 = (const float*)d_in[16];
    const float* m2  = (const float*)d_in[17];
    const float* v2  = (const float*)d_in[18];
    const float* lw0 = (const float*)d_in[19];
    const float* lb0 = (const float*)d_in[20];
    const float* lw1 = (const float*)d_in[21];
    const float* lb1 = (const float*)d_in[22];
    float* out = (float*)d_out;

    float* f0ptr;  cudaGetSymbolAddress((void**)&f0ptr, g_f0);
    float* f1ptr;  cudaGetSymbolAddress((void**)&f1ptr, g_f1);
    float* f2ptr;  cudaGetSymbolAddress((void**)&f2ptr, g_f2);
    float* preptr; cudaGetSymbolAddress((void**)&preptr, g_pre);
    __half* wc1h; cudaGetSymbolAddress((void**)&wc1h, g_wc1h);
    __half* wc1l; cudaGetSymbolAddress((void**)&wc1l, g_wc1l);
    __half* wc2h; cudaGetSymbolAddress((void**)&wc2h, g_wc2h);
    __half* wc2l; cudaGetSymbolAddress((void**)&wc2l, g_wc2l);
    __half* wphptr; cudaGetSymbolAddress((void**)&wphptr, g_wph);
    __half* wplptr; cudaGetSymbolAddress((void**)&wplptr, g_wpl);
    __half* bx0hptr; cudaGetSymbolAddress((void**)&bx0hptr, g_bx0h);
    __half* bx0lptr; cudaGetSymbolAddress((void**)&bx0lptr, g_bx0l);
    __half* bx1hptr; cudaGetSymbolAddress((void**)&bx1hptr, g_bx1h);
    __half* bx1lptr; cudaGetSymbolAddress((void**)&bx1lptr, g_bx1l);

    // weight prepacks
    prepack_w<<<18432, 256>>>(lw0, 0);
    prepack_w<<<18432, 256>>>(lw1, 1);
    prepack_cw<64, 128><<<288, 256>>>(w1, wc1h, wc1l);    // 36*128*16 = 73728
    prepack_cw<128, 256><<<1152, 256>>>(w2, wc2h, wc2l);  // 72*256*16 = 294912

    // CNN encoder
    conv0_pool<<<32768, 256>>>(x, w0, b0, g0, be0, m0, v0);
    // block1: N tiles 4096/128=32, mtiles 1, frames 32
    conv_mma<64, 64, 128><<<dim3(32, 1, 32), 256>>>(f0ptr, wc1h, wc1l,
                                                    b1, g1, be1, m1, v1, preptr);
    pool2<128, 64><<<16384, 256>>>(preptr, f1ptr);        // 4.19M outputs
    // block2: N tiles 1024/128=8, mtiles 2, frames 32
    conv_mma<128, 32, 256><<<dim3(8, 2, 32), 256>>>(f1ptr, wc2h, wc2l,
                                                    b2, g2, be2, m2, v2, preptr);
    pool2<256, 32><<<8192, 256>>>(preptr, f2ptr);         // 2.10M outputs

    // hi/lo fp16 im2col of CNN features
    build_bx0<<<73728, 256>>>();

    // ConvLSTM layer 0
    zero_state<<<4608, 256>>>();
    for (int t = 0; t < 16; t++) {
        lstm_mma<<<dim3(8, 4, 4), 256>>>(wphptr, wplptr,
                                         bx0hptr + (size_t)t * 2 * BHS,
                                         bx0lptr + (size_t)t * 2 * BHS);
        lstm_gates<<<512, 256>>>(t, 0, lb0, out);
    }

    // ConvLSTM layer 1
    zero_state<<<4608, 256>>>();
    for (int t = 0; t < 16; t++) {
        lstm_mma<<<dim3(8, 4, 4), 256>>>(wphptr + (size_t)288 * 1024 * 16,
                                         wplptr + (size_t)288 * 1024 * 16,
                                         bx1hptr + (size_t)t * 2 * BHS,
                                         bx1lptr + (size_t)t * 2 * BHS);
        lstm_gates<<<512, 256>>>(t, 1, lb1, out);
    }

    copy_last<<<512, 256>>>(out);
}